// round 1
// baseline (speedup 1.0000x reference)
#include <cuda_runtime.h>
#include <math.h>

#define HIDDEN 2048
#define NEXP 8
#define GDIM 64
#define BTOK 4096

// ---------------- device scratch (no allocations allowed) ----------------
__device__ int   g_cnt[NEXP];
__device__ int   g_tok[NEXP][BTOK];
__device__ float g_wt[NEXP][BTOK];
__device__ float g_psum[NEXP];

// ---------------- packed fp32x2 helpers (sm_103a) ----------------
__device__ __forceinline__ unsigned long long pack2(float lo, float hi) {
    unsigned long long r;
    asm("mov.b64 %0, {%1, %2};" : "=l"(r) : "f"(lo), "f"(hi));
    return r;
}
__device__ __forceinline__ void fma2(unsigned long long &d, unsigned long long a, unsigned long long b) {
    asm("fma.rn.f32x2 %0, %1, %2, %0;" : "+l"(d) : "l"(a), "l"(b));
}
__device__ __forceinline__ float2 unpack2(unsigned long long v) {
    float lo, hi;
    asm("mov.b64 {%0, %1}, %2;" : "=f"(lo), "=f"(hi) : "l"(v));
    return make_float2(lo, hi);
}

// ---------------- K0: zero counters ----------------
__global__ void init_kernel() {
    int t = threadIdx.x;
    if (t < NEXP) { g_cnt[t] = 0; g_psum[t] = 0.f; }
}

// ---------------- K1: gating (h-GEMM + softmax + noise + top2 + lists) ----------------
__global__ __launch_bounds__(256) void gating_kernel(
    const float* __restrict__ X, const float* __restrict__ noise,
    const float* __restrict__ gw1, const float* __restrict__ gb1,
    const float* __restrict__ gw2, const float* __restrict__ gb2)
{
    __shared__ float xs[32][68];      // 32 tokens x 64 k-slice
    __shared__ float hs[32][65];      // relu hidden
    __shared__ float lg[32][NEXP];    // logits -> noisy gating
    __shared__ float ws2[GDIM * NEXP];
    __shared__ float bs2[NEXP];

    const int tid  = threadIdx.x;
    const int tok0 = blockIdx.x * 32;
    const int j = tid & 63;   // gating dim
    const int r = tid >> 6;   // token sub-row 0..3

    ws2[tid]       = gw2[tid];
    ws2[tid + 256] = gw2[tid + 256];
    if (tid < NEXP) bs2[tid] = gb2[tid];

    float acc[8];
    const float b1 = gb1[j];
    #pragma unroll
    for (int u = 0; u < 8; u++) acc[u] = b1;

    for (int k0 = 0; k0 < HIDDEN; k0 += 64) {
        __syncthreads();
        #pragma unroll
        for (int rr = 0; rr < 2; rr++) {
            int idx = tid + rr * 256;
            int row = idx >> 4, q = (idx & 15) << 2;
            float4 v = *(const float4*)&X[(size_t)(tok0 + row) * HIDDEN + k0 + q];
            *(float4*)&xs[row][q] = v;
        }
        __syncthreads();
        #pragma unroll 8
        for (int kk = 0; kk < 64; kk++) {
            float w = gw1[(size_t)(k0 + kk) * GDIM + j];
            #pragma unroll
            for (int u = 0; u < 8; u++) acc[u] = fmaf(xs[r + 4 * u][kk], w, acc[u]);
        }
    }
    #pragma unroll
    for (int u = 0; u < 8; u++) hs[r + 4 * u][j] = fmaxf(acc[u], 0.f);
    __syncthreads();

    // logits: thread -> (token = tid>>3, expert = tid&7)
    {
        int lt = tid >> 3, e = tid & 7;
        float a = bs2[e];
        #pragma unroll 8
        for (int k = 0; k < GDIM; k++) a = fmaf(hs[lt][k], ws2[k * NEXP + e], a);
        lg[lt][e] = a;
    }
    __syncthreads();

    if (tid < 32) {
        int lt = tid;
        int token = tok0 + lt;
        float g[NEXP];
        float m = -1e30f;
        #pragma unroll
        for (int e = 0; e < NEXP; e++) { g[e] = lg[lt][e]; m = fmaxf(m, g[e]); }
        float s = 0.f;
        #pragma unroll
        for (int e = 0; e < NEXP; e++) { g[e] = expf(g[e] - m); s += g[e]; }
        float inv = 1.f / s;
        #pragma unroll
        for (int e = 0; e < NEXP; e++) {
            g[e] = g[e] * inv + noise[token * NEXP + e] * 0.01f;
            lg[lt][e] = g[e];
        }
        // top-1 (ties -> lowest index, matching jax.lax.top_k)
        int i1 = 0; float v1 = g[0];
        #pragma unroll
        for (int e = 1; e < NEXP; e++) if (g[e] > v1) { v1 = g[e]; i1 = e; }
        int i2 = -1; float v2 = -1e30f;
        #pragma unroll
        for (int e = 0; e < NEXP; e++) if (e != i1 && g[e] > v2) { v2 = g[e]; i2 = e; }
        float wsum = v1 + v2;
        float w1 = v1 / wsum, w2 = v2 / wsum;
        int p1 = atomicAdd(&g_cnt[i1], 1);
        g_tok[i1][p1] = token; g_wt[i1][p1] = w1;
        int p2 = atomicAdd(&g_cnt[i2], 1);
        g_tok[i2][p2] = token; g_wt[i2][p2] = w2;
    }
    __syncthreads();
    if (tid < NEXP) {
        float s = 0.f;
        #pragma unroll
        for (int t = 0; t < 32; t++) s += lg[t][tid];
        atomicAdd(&g_psum[tid], s);
    }
}

// ---------------- K2: shared GEMM + base epilogue ----------------
// out = (1+rs)*x + ss*sigmoid(x@Ws + bs)
__global__ __launch_bounds__(256, 2) void shared_gemm(
    const float* __restrict__ X, const float* __restrict__ W,
    const float* __restrict__ bias, const float* __restrict__ p_ss,
    const float* __restrict__ p_rs, float* __restrict__ out)
{
    __shared__ float As[16][132];
    __shared__ float Bs[16][132];
    const int tid = threadIdx.x;
    const int mb = blockIdx.x * 128;
    const int nb = blockIdx.y * 128;
    const int tx = tid & 15, ty = tid >> 4;

    unsigned long long acc[8][4];
    #pragma unroll
    for (int i = 0; i < 8; i++)
        #pragma unroll
        for (int jp = 0; jp < 4; jp++) acc[i][jp] = pack2(0.f, 0.f);

    for (int k0 = 0; k0 < HIDDEN; k0 += 16) {
        #pragma unroll
        for (int rr = 0; rr < 2; rr++) {
            int idx = tid + rr * 256;
            int arow = idx >> 2, aq = (idx & 3) << 2;
            float4 av = *(const float4*)&X[(size_t)(mb + arow) * HIDDEN + k0 + aq];
            As[aq + 0][arow] = av.x; As[aq + 1][arow] = av.y;
            As[aq + 2][arow] = av.z; As[aq + 3][arow] = av.w;
            int brow = idx >> 5, bq = (idx & 31) << 2;
            float4 bv = *(const float4*)&W[(size_t)(k0 + brow) * HIDDEN + nb + bq];
            *(float4*)&Bs[brow][bq] = bv;
        }
        __syncthreads();
        #pragma unroll
        for (int kk = 0; kk < 16; kk++) {
            float4 a0 = *(const float4*)&As[kk][ty * 8];
            float4 a1 = *(const float4*)&As[kk][ty * 8 + 4];
            float4 b0 = *(const float4*)&Bs[kk][tx * 8];
            float4 b1 = *(const float4*)&Bs[kk][tx * 8 + 4];
            unsigned long long bb[4] = { pack2(b0.x, b0.y), pack2(b0.z, b0.w),
                                         pack2(b1.x, b1.y), pack2(b1.z, b1.w) };
            float a[8] = { a0.x, a0.y, a0.z, a0.w, a1.x, a1.y, a1.z, a1.w };
            #pragma unroll
            for (int i = 0; i < 8; i++) {
                unsigned long long aa = pack2(a[i], a[i]);
                #pragma unroll
                for (int jp = 0; jp < 4; jp++) fma2(acc[i][jp], aa, bb[jp]);
            }
        }
        __syncthreads();
    }
    const float ss = p_ss[0], rs = p_rs[0];
    const float xscale = 1.f + rs;
    #pragma unroll
    for (int i = 0; i < 8; i++) {
        int row = mb + ty * 8 + i;
        #pragma unroll
        for (int jp = 0; jp < 4; jp++) {
            float2 v = unpack2(acc[i][jp]);
            int col = nb + tx * 8 + jp * 2;
            float s0 = 1.f / (1.f + __expf(-(v.x + bias[col])));
            float s1 = 1.f / (1.f + __expf(-(v.y + bias[col + 1])));
            float2 xv = *(const float2*)&X[(size_t)row * HIDDEN + col];
            float2 ov;
            ov.x = xscale * xv.x + ss * s0;
            ov.y = xscale * xv.y + ss * s1;
            *(float2*)&out[(size_t)row * HIDDEN + col] = ov;
        }
    }
}

// ---------------- K3: grouped expert GEMM, scatter-add epilogue ----------------
__global__ __launch_bounds__(256, 2) void expert_gemm(
    const float* __restrict__ X, const float* __restrict__ Wall,
    const float* __restrict__ Ball, const float* __restrict__ p_rs,
    float* __restrict__ out)
{
    const int e = blockIdx.z;
    const int cnt = g_cnt[e];
    const int mb = blockIdx.x * 128;
    if (mb >= cnt) return;
    const int nb = blockIdx.y * 128;
    const float* W    = Wall + (size_t)e * HIDDEN * HIDDEN;
    const float* bias = Ball + (size_t)e * HIDDEN;

    __shared__ float As[16][132];
    __shared__ float Bs[16][132];
    __shared__ int   toks[128];
    __shared__ float wts[128];

    const int tid = threadIdx.x;
    const int tx = tid & 15, ty = tid >> 4;

    if (tid < 128) {
        int li = mb + tid;
        toks[tid] = (li < cnt) ? g_tok[e][li] : 0;
        wts[tid]  = (li < cnt) ? g_wt[e][li] : 0.f;
    }
    __syncthreads();

    unsigned long long acc[8][4];
    #pragma unroll
    for (int i = 0; i < 8; i++)
        #pragma unroll
        for (int jp = 0; jp < 4; jp++) acc[i][jp] = pack2(0.f, 0.f);

    for (int k0 = 0; k0 < HIDDEN; k0 += 16) {
        #pragma unroll
        for (int rr = 0; rr < 2; rr++) {
            int idx = tid + rr * 256;
            int arow = idx >> 2, aq = (idx & 3) << 2;
            int tok = toks[arow];
            float4 av = *(const float4*)&X[(size_t)tok * HIDDEN + k0 + aq];
            As[aq + 0][arow] = av.x; As[aq + 1][arow] = av.y;
            As[aq + 2][arow] = av.z; As[aq + 3][arow] = av.w;
            int brow = idx >> 5, bq = (idx & 31) << 2;
            float4 bv = *(const float4*)&W[(size_t)(k0 + brow) * HIDDEN + nb + bq];
            *(float4*)&Bs[brow][bq] = bv;
        }
        __syncthreads();
        #pragma unroll
        for (int kk = 0; kk < 16; kk++) {
            float4 a0 = *(const float4*)&As[kk][ty * 8];
            float4 a1 = *(const float4*)&As[kk][ty * 8 + 4];
            float4 b0 = *(const float4*)&Bs[kk][tx * 8];
            float4 b1 = *(const float4*)&Bs[kk][tx * 8 + 4];
            unsigned long long bb[4] = { pack2(b0.x, b0.y), pack2(b0.z, b0.w),
                                         pack2(b1.x, b1.y), pack2(b1.z, b1.w) };
            float a[8] = { a0.x, a0.y, a0.z, a0.w, a1.x, a1.y, a1.z, a1.w };
            #pragma unroll
            for (int i = 0; i < 8; i++) {
                unsigned long long aa = pack2(a[i], a[i]);
                #pragma unroll
                for (int jp = 0; jp < 4; jp++) fma2(acc[i][jp], aa, bb[jp]);
            }
        }
        __syncthreads();
    }

    const float rs = p_rs[0];
    #pragma unroll
    for (int i = 0; i < 8; i++) {
        int lr = ty * 8 + i;
        if (mb + lr >= cnt) continue;
        int tok = toks[lr];
        float scale = rs * wts[lr];
        #pragma unroll
        for (int jp = 0; jp < 4; jp++) {
            float2 v = unpack2(acc[i][jp]);
            int col = nb + tx * 8 + jp * 2;
            float s0 = 1.f / (1.f + __expf(-(v.x + bias[col])));
            float s1 = 1.f / (1.f + __expf(-(v.y + bias[col + 1])));
            atomicAdd(&out[(size_t)tok * HIDDEN + col],     scale * s0);
            atomicAdd(&out[(size_t)tok * HIDDEN + col + 1], scale * s1);
        }
    }
}

// ---------------- K4: gate loss ----------------
__global__ void loss_kernel(float* __restrict__ out, int out_size) {
    if (threadIdx.x == 0) {
        float acc = 0.f;
        #pragma unroll
        for (int e = 0; e < NEXP; e++) {
            float p = g_psum[e] * (1.f / (float)BTOK);
            float d = 0.125f - p;
            acc += d * d;
        }
        float loss = acc * (0.01f / 8.f);
        for (long long i = (long long)BTOK * HIDDEN; i < out_size; i++)
            out[i] = loss;
    }
}

// ---------------- launcher ----------------
extern "C" void kernel_launch(void* const* d_in, const int* in_sizes, int n_in,
                              void* d_out, int out_size) {
    const float* x      = (const float*)d_in[0];
    const float* noise  = (const float*)d_in[1];
    const float* gw1    = (const float*)d_in[2];
    const float* gb1    = (const float*)d_in[3];
    const float* gw2    = (const float*)d_in[4];
    const float* gb2    = (const float*)d_in[5];
    const float* sw     = (const float*)d_in[6];
    const float* sb     = (const float*)d_in[7];
    const float* sscale = (const float*)d_in[8];
    const float* ew     = (const float*)d_in[9];
    const float* eb     = (const float*)d_in[10];
    const float* rscale = (const float*)d_in[11];
    float* out = (float*)d_out;

    init_kernel<<<1, 32>>>();
    gating_kernel<<<128, 256>>>(x, noise, gw1, gb1, gw2, gb2);
    shared_gemm<<<dim3(32, 16), 256>>>(x, sw, sb, sscale, rscale, out);
    expert_gemm<<<dim3(32, 16, 8), 256>>>(x, ew, eb, rscale, out);
    loss_kernel<<<1, 32>>>(out, out_size);
}

// round 3
// speedup vs baseline: 2.5354x; 2.5354x over previous
#include <cuda_runtime.h>
#include <cstdint>
#include <math.h>

#define HIDDEN 2048
#define NEXP 8
#define GDIM 64
#define BTOK 4096

#define TILE_M 128
#define TILE_N 256
#define BK 32
#define NCHUNKS (HIDDEN / BK)       // 64
#define NSTAGE 3

#define SA 36                        // A smem row stride (floats) -> 144B
#define SB 260                       // B smem row stride (floats) -> 1040B
#define A_STAGE_BYTES (128 * SA * 4) // 18432
#define B_STAGE_BYTES (BK * SB * 4)  // 33280
#define STAGE_BYTES (A_STAGE_BYTES + B_STAGE_BYTES) // 51712
#define SMEM_HDR 1024
#define SMEM_TOTAL (SMEM_HDR + NSTAGE * STAGE_BYTES) // 156160

// ---------------- device scratch ----------------
__device__ int   g_cnt[NEXP];
__device__ int   g_tok[NEXP][BTOK];
__device__ float g_wt[NEXP][BTOK];
__device__ float g_psum[NEXP];

// ---------------- helpers ----------------
__device__ __forceinline__ uint32_t smem_u32(const void* p) {
    uint32_t a;
    asm("{ .reg .u64 t; cvta.to.shared.u64 t, %1; cvt.u32.u64 %0, t; }" : "=r"(a) : "l"(p));
    return a;
}
__device__ __forceinline__ void cp16(uint32_t dst, const void* src) {
    asm volatile("cp.async.cg.shared.global [%0], [%1], 16;" :: "r"(dst), "l"(src));
}
#define CP_COMMIT() asm volatile("cp.async.commit_group;" ::: "memory")
#define CP_WAIT(n)  asm volatile("cp.async.wait_group %0;" :: "n"(n) : "memory")

__device__ __forceinline__ uint32_t to_tf32(float v) {
    uint32_t u;
    asm("cvt.rna.tf32.f32 %0, %1;" : "=r"(u) : "f"(v));
    return u;
}
__device__ __forceinline__ void mma_tf32(float* d, const uint32_t* a, const uint32_t* b) {
    asm volatile(
        "mma.sync.aligned.m16n8k8.row.col.f32.tf32.tf32.f32 "
        "{%0,%1,%2,%3}, {%4,%5,%6,%7}, {%8,%9}, {%0,%1,%2,%3};"
        : "+f"(d[0]), "+f"(d[1]), "+f"(d[2]), "+f"(d[3])
        : "r"(a[0]), "r"(a[1]), "r"(a[2]), "r"(a[3]), "r"(b[0]), "r"(b[1]));
}
__device__ __forceinline__ void red_add_v2(float* p, float a, float b) {
    asm volatile("red.global.add.v2.f32 [%0], {%1, %2};" :: "l"(p), "f"(a), "f"(b) : "memory");
}
__device__ __forceinline__ float sigf(float z) { return 1.f / (1.f + __expf(-z)); }

// ---------------- K0: zero counters ----------------
__global__ void init_kernel() {
    int t = threadIdx.x;
    if (t < NEXP) { g_cnt[t] = 0; g_psum[t] = 0.f; }
}

// ---------------- K1: gating ----------------
__global__ __launch_bounds__(256) void gating_kernel(
    const float* __restrict__ X, const float* __restrict__ noise,
    const float* __restrict__ gw1, const float* __restrict__ gb1,
    const float* __restrict__ gw2, const float* __restrict__ gb2)
{
    __shared__ float xs[32][68];
    __shared__ float hs[32][65];
    __shared__ float lg[32][NEXP];
    __shared__ float ws2[GDIM * NEXP];
    __shared__ float bs2[NEXP];

    const int tid  = threadIdx.x;
    const int tok0 = blockIdx.x * 32;
    const int j = tid & 63;
    const int r = tid >> 6;

    ws2[tid]       = gw2[tid];
    ws2[tid + 256] = gw2[tid + 256];
    if (tid < NEXP) bs2[tid] = gb2[tid];

    float acc[8];
    const float b1 = gb1[j];
    #pragma unroll
    for (int u = 0; u < 8; u++) acc[u] = b1;

    for (int k0 = 0; k0 < HIDDEN; k0 += 64) {
        __syncthreads();
        #pragma unroll
        for (int rr = 0; rr < 2; rr++) {
            int idx = tid + rr * 256;
            int row = idx >> 4, q = (idx & 15) << 2;
            float4 v = *(const float4*)&X[(size_t)(tok0 + row) * HIDDEN + k0 + q];
            *(float4*)&xs[row][q] = v;
        }
        __syncthreads();
        #pragma unroll 8
        for (int kk = 0; kk < 64; kk++) {
            float w = gw1[(size_t)(k0 + kk) * GDIM + j];
            #pragma unroll
            for (int u = 0; u < 8; u++) acc[u] = fmaf(xs[r + 4 * u][kk], w, acc[u]);
        }
    }
    #pragma unroll
    for (int u = 0; u < 8; u++) hs[r + 4 * u][j] = fmaxf(acc[u], 0.f);
    __syncthreads();

    {
        int lt = tid >> 3, e = tid & 7;
        float a = bs2[e];
        #pragma unroll 8
        for (int k = 0; k < GDIM; k++) a = fmaf(hs[lt][k], ws2[k * NEXP + e], a);
        lg[lt][e] = a;
    }
    __syncthreads();

    if (tid < 32) {
        int lt = tid;
        int token = tok0 + lt;
        float g[NEXP];
        float m = -1e30f;
        #pragma unroll
        for (int e = 0; e < NEXP; e++) { g[e] = lg[lt][e]; m = fmaxf(m, g[e]); }
        float s = 0.f;
        #pragma unroll
        for (int e = 0; e < NEXP; e++) { g[e] = expf(g[e] - m); s += g[e]; }
        float inv = 1.f / s;
        #pragma unroll
        for (int e = 0; e < NEXP; e++) {
            g[e] = g[e] * inv + noise[token * NEXP + e] * 0.01f;
            lg[lt][e] = g[e];
        }
        int i1 = 0; float v1 = g[0];
        #pragma unroll
        for (int e = 1; e < NEXP; e++) if (g[e] > v1) { v1 = g[e]; i1 = e; }
        int i2 = -1; float v2 = -1e30f;
        #pragma unroll
        for (int e = 0; e < NEXP; e++) if (e != i1 && g[e] > v2) { v2 = g[e]; i2 = e; }
        float wsum = v1 + v2;
        float w1 = v1 / wsum, w2 = v2 / wsum;
        int p1 = atomicAdd(&g_cnt[i1], 1);
        g_tok[i1][p1] = token; g_wt[i1][p1] = w1;
        int p2 = atomicAdd(&g_cnt[i2], 1);
        g_tok[i2][p2] = token; g_wt[i2][p2] = w2;
    }
    __syncthreads();
    if (tid < NEXP) {
        float s = 0.f;
        #pragma unroll
        for (int t = 0; t < 32; t++) s += lg[t][tid];
        atomicAdd(&g_psum[tid], s);
    }
}

// ---------------- stage loader ----------------
template<bool EXPERT>
__device__ __forceinline__ void load_stage(
    const float* __restrict__ X, const float* __restrict__ W,
    int nb, int mb, const int* __restrict__ toks,
    uint32_t smem_base, int chunk, int buf, int tid)
{
    const uint32_t abase = smem_base + SMEM_HDR + buf * STAGE_BYTES;
    const uint32_t bbase = abase + A_STAGE_BYTES;
    const int k0 = chunk * BK;

    // A: 128 rows x 32 floats
    #pragma unroll
    for (int j = 0; j < 4; j++) {
        int idx = tid + j * 256;
        int row = idx >> 3, c = idx & 7;
        int tok = EXPERT ? toks[row] : (mb + row);
        cp16(abase + (uint32_t)(row * 144 + c * 16),
             X + (size_t)tok * HIDDEN + k0 + c * 4);
    }
    // B: 32 k-rows x 256 n floats
    #pragma unroll
    for (int j = 0; j < 8; j++) {
        int idx = tid + j * 256;
        int row = idx >> 6, c = idx & 63;
        cp16(bbase + (uint32_t)(row * 1040 + c * 16),
             W + (size_t)(k0 + row) * HIDDEN + nb + c * 4);
    }
    CP_COMMIT();
}

// ---------------- GEMM tile body (mma.sync tf32) ----------------
template<bool EXPERT>
__device__ __forceinline__ void gemm_tile(
    const float* __restrict__ X, const float* __restrict__ W,
    const float* __restrict__ bias, float sc1 /*ss or rs*/, float xscale,
    float* __restrict__ out, int mb, int nb, int cnt, int e)
{
    extern __shared__ char smem[];
    const uint32_t smem_base = smem_u32(smem);
    const int tid = threadIdx.x;
    const int wid = tid >> 5;
    const int lane = tid & 31;
    const int wm = wid & 1;          // M half: 0/1
    const int wn = wid >> 1;         // N quarter: 0..3

    int*   toks = (int*)smem;
    float* wts  = (float*)(smem + 512);

    if (EXPERT) {
        if (tid < 128) {
            int li = mb + tid;
            toks[tid] = (li < cnt) ? g_tok[e][li] : 0;
            wts[tid]  = (li < cnt) ? g_wt[e][li] : 0.f;
        }
        __syncthreads();
    }

    float acc[4][8][4];
    #pragma unroll
    for (int mt = 0; mt < 4; mt++)
        #pragma unroll
        for (int nt = 0; nt < 8; nt++)
            #pragma unroll
            for (int q = 0; q < 4; q++) acc[mt][nt][q] = 0.f;

    // prologue: 2 stages
    load_stage<EXPERT>(X, W, nb, mb, toks, smem_base, 0, 0, tid);
    load_stage<EXPERT>(X, W, nb, mb, toks, smem_base, 1, 1, tid);

    const int lq = lane >> 2;   // 0..7
    const int lr = lane & 3;    // 0..3

    for (int i = 0; i < NCHUNKS; i++) {
        const int buf = i % NSTAGE;
        CP_WAIT(1);
        __syncthreads();

        if (i + 2 < NCHUNKS)
            load_stage<EXPERT>(X, W, nb, mb, toks, smem_base, i + 2, (i + 2) % NSTAGE, tid);

        const float* As = (const float*)(smem + SMEM_HDR + buf * STAGE_BYTES);
        const float* Bs = (const float*)(smem + SMEM_HDR + buf * STAGE_BYTES + A_STAGE_BYTES);

        #pragma unroll
        for (int ks = 0; ks < 4; ks++) {
            uint32_t af[4][4];
            #pragma unroll
            for (int mt = 0; mt < 4; mt++) {
                int r0 = wm * 64 + mt * 16 + lq;
                int cc = ks * 8 + lr;
                af[mt][0] = to_tf32(As[r0 * SA + cc]);
                af[mt][1] = to_tf32(As[(r0 + 8) * SA + cc]);
                af[mt][2] = to_tf32(As[r0 * SA + cc + 4]);
                af[mt][3] = to_tf32(As[(r0 + 8) * SA + cc + 4]);
            }
            uint32_t bf[8][2];
            #pragma unroll
            for (int nt = 0; nt < 8; nt++) {
                int kk = ks * 8 + lr;
                int nn = wn * 64 + nt * 8 + lq;
                bf[nt][0] = to_tf32(Bs[kk * SB + nn]);
                bf[nt][1] = to_tf32(Bs[(kk + 4) * SB + nn]);
            }
            #pragma unroll
            for (int mt = 0; mt < 4; mt++)
                #pragma unroll
                for (int nt = 0; nt < 8; nt++)
                    mma_tf32(acc[mt][nt], af[mt], bf[nt]);
        }
        __syncthreads();
    }

    // ---------------- epilogue ----------------
    #pragma unroll
    for (int mt = 0; mt < 4; mt++) {
        #pragma unroll
        for (int h = 0; h < 2; h++) {
            int mrow = wm * 64 + mt * 16 + lq + h * 8;
            if (EXPERT) {
                if (mb + mrow >= cnt) continue;
                int token = toks[mrow];
                float wscale = sc1 * wts[mrow];
                float* orow = out + (size_t)token * HIDDEN;
                #pragma unroll
                for (int nt = 0; nt < 8; nt++) {
                    int col = nb + wn * 64 + nt * 8 + 2 * lr;
                    float2 bv = *(const float2*)&bias[col];
                    float s0 = wscale * sigf(acc[mt][nt][2 * h]     + bv.x);
                    float s1 = wscale * sigf(acc[mt][nt][2 * h + 1] + bv.y);
                    red_add_v2(orow + col, s0, s1);
                }
            } else {
                int grow = mb + mrow;
                const float* xr = X + (size_t)grow * HIDDEN;
                float* orow = out + (size_t)grow * HIDDEN;
                #pragma unroll
                for (int nt = 0; nt < 8; nt++) {
                    int col = nb + wn * 64 + nt * 8 + 2 * lr;
                    float2 bv = *(const float2*)&bias[col];
                    float2 xv = *(const float2*)&xr[col];
                    float2 ov;
                    ov.x = xscale * xv.x + sc1 * sigf(acc[mt][nt][2 * h]     + bv.x);
                    ov.y = xscale * xv.y + sc1 * sigf(acc[mt][nt][2 * h + 1] + bv.y);
                    *(float2*)&orow[col] = ov;
                }
            }
        }
    }
}

// ---------------- K2: shared GEMM + base epilogue ----------------
__global__ __launch_bounds__(256, 1)
void shared_gemm(const float* __restrict__ X, const float* __restrict__ W,
                 const float* __restrict__ bias, const float* __restrict__ p_ss,
                 const float* __restrict__ p_rs, float* __restrict__ out)
{
    const int mb = blockIdx.x * TILE_M;
    const int nb = blockIdx.y * TILE_N;
    gemm_tile<false>(X, W, bias, p_ss[0], 1.f + p_rs[0], out, mb, nb, BTOK, 0);
}

// ---------------- K3: expert grouped GEMM ----------------
__global__ __launch_bounds__(256, 1)
void expert_gemm(const float* __restrict__ X, const float* __restrict__ Wall,
                 const float* __restrict__ Ball, const float* __restrict__ p_rs,
                 float* __restrict__ out)
{
    const int e = blockIdx.z;
    const int cnt = g_cnt[e];
    const int mb = blockIdx.x * TILE_M;
    if (mb >= cnt) return;
    const int nb = blockIdx.y * TILE_N;
    const float* W    = Wall + (size_t)e * HIDDEN * HIDDEN;
    const float* bias = Ball + (size_t)e * HIDDEN;
    gemm_tile<true>(X, W, bias, p_rs[0], 0.f, out, mb, nb, cnt, e);
}

// ---------------- K4: gate loss ----------------
__global__ void loss_kernel(float* __restrict__ out, int out_size) {
    if (threadIdx.x == 0) {
        float acc = 0.f;
        #pragma unroll
        for (int e = 0; e < NEXP; e++) {
            float p = g_psum[e] * (1.f / (float)BTOK);
            float d = 0.125f - p;
            acc += d * d;
        }
        float loss = acc * (0.01f / 8.f);
        for (long long i = (long long)BTOK * HIDDEN; i < out_size; i++)
            out[i] = loss;
    }
}

// ---------------- launcher ----------------
extern "C" void kernel_launch(void* const* d_in, const int* in_sizes, int n_in,
                              void* d_out, int out_size) {
    const float* x      = (const float*)d_in[0];
    const float* noise  = (const float*)d_in[1];
    const float* gw1    = (const float*)d_in[2];
    const float* gb1    = (const float*)d_in[3];
    const float* gw2    = (const float*)d_in[4];
    const float* gb2    = (const float*)d_in[5];
    const float* sw     = (const float*)d_in[6];
    const float* sb     = (const float*)d_in[7];
    const float* sscale = (const float*)d_in[8];
    const float* ew     = (const float*)d_in[9];
    const float* eb     = (const float*)d_in[10];
    const float* rscale = (const float*)d_in[11];
    float* out = (float*)d_out;

    static bool attr_done = false;
    if (!attr_done) {
        cudaFuncSetAttribute(shared_gemm, cudaFuncAttributeMaxDynamicSharedMemorySize, SMEM_TOTAL);
        cudaFuncSetAttribute(expert_gemm, cudaFuncAttributeMaxDynamicSharedMemorySize, SMEM_TOTAL);
        attr_done = true;
    }

    init_kernel<<<1, 32>>>();
    gating_kernel<<<128, 256>>>(x, noise, gw1, gb1, gw2, gb2);
    shared_gemm<<<dim3(BTOK / TILE_M, HIDDEN / TILE_N), 256, SMEM_TOTAL>>>(
        x, sw, sb, sscale, rscale, out);
    expert_gemm<<<dim3(BTOK / TILE_M, HIDDEN / TILE_N, NEXP), 256, SMEM_TOTAL>>>(
        x, ew, eb, rscale, out);
    loss_kernel<<<1, 32>>>(out, out_size);
}

// round 4
// speedup vs baseline: 2.9056x; 1.1460x over previous
#include <cuda_runtime.h>
#include <cstdint>
#include <math.h>

#define HIDDEN 2048
#define NEXP 8
#define GDIM 64
#define BTOK 4096

#define TILE_M 128
#define TILE_N 128
#define BK 32
#define NCHUNKS (HIDDEN / BK)       // 64
#define NSTAGE 3

#define SA 36                        // A smem row stride (floats) -> 144B, conflict-free
#define SB 136                       // B smem row stride (floats) -> 544B, conflict-free (136%32==8)
#define A_STAGE_BYTES (128 * SA * 4) // 18432
#define B_STAGE_BYTES (BK * SB * 4)  // 17408
#define STAGE_BYTES (A_STAGE_BYTES + B_STAGE_BYTES) // 35840
#define SMEM_HDR 1024
#define SMEM_TOTAL (SMEM_HDR + NSTAGE * STAGE_BYTES) // 108544 -> 2 CTAs/SM

// ---------------- device scratch ----------------
__device__ int   g_cnt[NEXP];
__device__ int   g_tok[NEXP][BTOK];
__device__ float g_wt[NEXP][BTOK];
__device__ float g_psum[NEXP];

// ---------------- helpers ----------------
__device__ __forceinline__ uint32_t smem_u32(const void* p) {
    uint32_t a;
    asm("{ .reg .u64 t; cvta.to.shared.u64 t, %1; cvt.u32.u64 %0, t; }" : "=r"(a) : "l"(p));
    return a;
}
__device__ __forceinline__ void cp16(uint32_t dst, const void* src) {
    asm volatile("cp.async.cg.shared.global [%0], [%1], 16;" :: "r"(dst), "l"(src));
}
#define CP_COMMIT() asm volatile("cp.async.commit_group;" ::: "memory")
#define CP_WAIT(n)  asm volatile("cp.async.wait_group %0;" :: "n"(n) : "memory")

__device__ __forceinline__ void mma_tf32(float* d, const uint32_t* a, const uint32_t* b) {
    asm volatile(
        "mma.sync.aligned.m16n8k8.row.col.f32.tf32.tf32.f32 "
        "{%0,%1,%2,%3}, {%4,%5,%6,%7}, {%8,%9}, {%0,%1,%2,%3};"
        : "+f"(d[0]), "+f"(d[1]), "+f"(d[2]), "+f"(d[3])
        : "r"(a[0]), "r"(a[1]), "r"(a[2]), "r"(a[3]), "r"(b[0]), "r"(b[1]));
}
__device__ __forceinline__ void red_add_v2(float* p, float a, float b) {
    asm volatile("red.global.add.v2.f32 [%0], {%1, %2};" :: "l"(p), "f"(a), "f"(b) : "memory");
}
__device__ __forceinline__ float sigf(float z) { return 1.f / (1.f + __expf(-z)); }

// ---------------- K0: zero counters ----------------
__global__ void init_kernel() {
    int t = threadIdx.x;
    if (t < NEXP) { g_cnt[t] = 0; g_psum[t] = 0.f; }
}

// ---------------- K1: gating ----------------
__global__ __launch_bounds__(256) void gating_kernel(
    const float* __restrict__ X, const float* __restrict__ noise,
    const float* __restrict__ gw1, const float* __restrict__ gb1,
    const float* __restrict__ gw2, const float* __restrict__ gb2)
{
    __shared__ float xs[32][68];
    __shared__ float hs[32][65];
    __shared__ float lg[32][NEXP];
    __shared__ float ws2[GDIM * NEXP];
    __shared__ float bs2[NEXP];

    const int tid  = threadIdx.x;
    const int tok0 = blockIdx.x * 32;
    const int j = tid & 63;
    const int r = tid >> 6;

    ws2[tid]       = gw2[tid];
    ws2[tid + 256] = gw2[tid + 256];
    if (tid < NEXP) bs2[tid] = gb2[tid];

    float acc[8];
    const float b1 = gb1[j];
    #pragma unroll
    for (int u = 0; u < 8; u++) acc[u] = b1;

    for (int k0 = 0; k0 < HIDDEN; k0 += 64) {
        __syncthreads();
        #pragma unroll
        for (int rr = 0; rr < 2; rr++) {
            int idx = tid + rr * 256;
            int row = idx >> 4, q = (idx & 15) << 2;
            float4 v = *(const float4*)&X[(size_t)(tok0 + row) * HIDDEN + k0 + q];
            *(float4*)&xs[row][q] = v;
        }
        __syncthreads();
        #pragma unroll 8
        for (int kk = 0; kk < 64; kk++) {
            float w = gw1[(size_t)(k0 + kk) * GDIM + j];
            #pragma unroll
            for (int u = 0; u < 8; u++) acc[u] = fmaf(xs[r + 4 * u][kk], w, acc[u]);
        }
    }
    #pragma unroll
    for (int u = 0; u < 8; u++) hs[r + 4 * u][j] = fmaxf(acc[u], 0.f);
    __syncthreads();

    {
        int lt = tid >> 3, e = tid & 7;
        float a = bs2[e];
        #pragma unroll 8
        for (int k = 0; k < GDIM; k++) a = fmaf(hs[lt][k], ws2[k * NEXP + e], a);
        lg[lt][e] = a;
    }
    __syncthreads();

    if (tid < 32) {
        int lt = tid;
        int token = tok0 + lt;
        float g[NEXP];
        float m = -1e30f;
        #pragma unroll
        for (int e = 0; e < NEXP; e++) { g[e] = lg[lt][e]; m = fmaxf(m, g[e]); }
        float s = 0.f;
        #pragma unroll
        for (int e = 0; e < NEXP; e++) { g[e] = expf(g[e] - m); s += g[e]; }
        float inv = 1.f / s;
        #pragma unroll
        for (int e = 0; e < NEXP; e++) {
            g[e] = g[e] * inv + noise[token * NEXP + e] * 0.01f;
            lg[lt][e] = g[e];
        }
        int i1 = 0; float v1 = g[0];
        #pragma unroll
        for (int e = 1; e < NEXP; e++) if (g[e] > v1) { v1 = g[e]; i1 = e; }
        int i2 = -1; float v2 = -1e30f;
        #pragma unroll
        for (int e = 0; e < NEXP; e++) if (e != i1 && g[e] > v2) { v2 = g[e]; i2 = e; }
        float wsum = v1 + v2;
        float w1 = v1 / wsum, w2 = v2 / wsum;
        int p1 = atomicAdd(&g_cnt[i1], 1);
        g_tok[i1][p1] = token; g_wt[i1][p1] = w1;
        int p2 = atomicAdd(&g_cnt[i2], 1);
        g_tok[i2][p2] = token; g_wt[i2][p2] = w2;
    }
    __syncthreads();
    if (tid < NEXP) {
        float s = 0.f;
        #pragma unroll
        for (int t = 0; t < 32; t++) s += lg[t][tid];
        atomicAdd(&g_psum[tid], s);
    }
}

// ---------------- stage loader ----------------
template<bool EXPERT>
__device__ __forceinline__ void load_stage(
    const float* __restrict__ X, const float* __restrict__ W,
    int nb, int mb, const int* __restrict__ toks,
    uint32_t smem_base, int chunk, int buf, int tid)
{
    const uint32_t abase = smem_base + SMEM_HDR + buf * STAGE_BYTES;
    const uint32_t bbase = abase + A_STAGE_BYTES;
    const int k0 = chunk * BK;

    // A: 128 rows x 32 floats (8x16B per row)
    #pragma unroll
    for (int j = 0; j < 4; j++) {
        int idx = tid + j * 256;
        int row = idx >> 3, c = idx & 7;
        int tok = EXPERT ? toks[row] : (mb + row);
        cp16(abase + (uint32_t)(row * (SA * 4) + c * 16),
             X + (size_t)tok * HIDDEN + k0 + c * 4);
    }
    // B: 32 k-rows x 128 n floats (32x16B per row)
    #pragma unroll
    for (int j = 0; j < 4; j++) {
        int idx = tid + j * 256;
        int row = idx >> 5, c = idx & 31;
        cp16(bbase + (uint32_t)(row * (SB * 4) + c * 16),
             W + (size_t)(k0 + row) * HIDDEN + nb + c * 4);
    }
    CP_COMMIT();
}

// ---------------- GEMM tile body (mma.sync tf32, 128x128, 8 warps, warp 64x32) ----------------
template<bool EXPERT>
__device__ __forceinline__ void gemm_tile(
    const float* __restrict__ X, const float* __restrict__ W,
    const float* __restrict__ bias, float sc1 /*ss or rs*/, float xscale,
    float* __restrict__ out, int mb, int nb, int cnt, int e)
{
    extern __shared__ char smem[];
    const uint32_t smem_base = smem_u32(smem);
    const int tid = threadIdx.x;
    const int wid = tid >> 5;
    const int lane = tid & 31;
    const int wm = wid & 1;          // M half: 0/1 (64 rows each)
    const int wn = wid >> 1;         // N quarter: 0..3 (32 cols each)

    int*   toks = (int*)smem;
    float* wts  = (float*)(smem + 512);

    if (EXPERT) {
        if (tid < 128) {
            int li = mb + tid;
            toks[tid] = (li < cnt) ? g_tok[e][li] : 0;
            wts[tid]  = (li < cnt) ? g_wt[e][li] : 0.f;
        }
        __syncthreads();
    }

    float acc[4][4][4];
    #pragma unroll
    for (int mt = 0; mt < 4; mt++)
        #pragma unroll
        for (int nt = 0; nt < 4; nt++)
            #pragma unroll
            for (int q = 0; q < 4; q++) acc[mt][nt][q] = 0.f;

    load_stage<EXPERT>(X, W, nb, mb, toks, smem_base, 0, 0, tid);
    load_stage<EXPERT>(X, W, nb, mb, toks, smem_base, 1, 1, tid);

    const int lq = lane >> 2;   // 0..7
    const int lr = lane & 3;    // 0..3

    for (int i = 0; i < NCHUNKS; i++) {
        const int buf = i % NSTAGE;
        CP_WAIT(1);
        __syncthreads();

        if (i + 2 < NCHUNKS)
            load_stage<EXPERT>(X, W, nb, mb, toks, smem_base, i + 2, (i + 2) % NSTAGE, tid);

        const float* As = (const float*)(smem + SMEM_HDR + buf * STAGE_BYTES);
        const float* Bs = (const float*)(smem + SMEM_HDR + buf * STAGE_BYTES + A_STAGE_BYTES);

        #pragma unroll
        for (int ks = 0; ks < 4; ks++) {
            uint32_t af[4][4];
            #pragma unroll
            for (int mt = 0; mt < 4; mt++) {
                int r0 = wm * 64 + mt * 16 + lq;
                int cc = ks * 8 + lr;
                af[mt][0] = __float_as_uint(As[r0 * SA + cc]);
                af[mt][1] = __float_as_uint(As[(r0 + 8) * SA + cc]);
                af[mt][2] = __float_as_uint(As[r0 * SA + cc + 4]);
                af[mt][3] = __float_as_uint(As[(r0 + 8) * SA + cc + 4]);
            }
            uint32_t bf[4][2];
            #pragma unroll
            for (int nt = 0; nt < 4; nt++) {
                int kk = ks * 8 + lr;
                int nn = wn * 32 + nt * 8 + lq;
                bf[nt][0] = __float_as_uint(Bs[kk * SB + nn]);
                bf[nt][1] = __float_as_uint(Bs[(kk + 4) * SB + nn]);
            }
            #pragma unroll
            for (int mt = 0; mt < 4; mt++)
                #pragma unroll
                for (int nt = 0; nt < 4; nt++)
                    mma_tf32(acc[mt][nt], af[mt], bf[nt]);
        }
        __syncthreads();
    }

    // ---------------- epilogue ----------------
    #pragma unroll
    for (int mt = 0; mt < 4; mt++) {
        #pragma unroll
        for (int h = 0; h < 2; h++) {
            int mrow = wm * 64 + mt * 16 + lq + h * 8;
            if (EXPERT) {
                if (mb + mrow >= cnt) continue;
                int token = toks[mrow];
                float wscale = sc1 * wts[mrow];
                float* orow = out + (size_t)token * HIDDEN;
                #pragma unroll
                for (int nt = 0; nt < 4; nt++) {
                    int col = nb + wn * 32 + nt * 8 + 2 * lr;
                    float2 bv = *(const float2*)&bias[col];
                    float s0 = wscale * sigf(acc[mt][nt][2 * h]     + bv.x);
                    float s1 = wscale * sigf(acc[mt][nt][2 * h + 1] + bv.y);
                    red_add_v2(orow + col, s0, s1);
                }
            } else {
                int grow = mb + mrow;
                const float* xr = X + (size_t)grow * HIDDEN;
                float* orow = out + (size_t)grow * HIDDEN;
                #pragma unroll
                for (int nt = 0; nt < 4; nt++) {
                    int col = nb + wn * 32 + nt * 8 + 2 * lr;
                    float2 bv = *(const float2*)&bias[col];
                    float2 xv = *(const float2*)&xr[col];
                    float2 ov;
                    ov.x = xscale * xv.x + sc1 * sigf(acc[mt][nt][2 * h]     + bv.x);
                    ov.y = xscale * xv.y + sc1 * sigf(acc[mt][nt][2 * h + 1] + bv.y);
                    *(float2*)&orow[col] = ov;
                }
            }
        }
    }
}

// ---------------- K2: shared GEMM + base epilogue ----------------
__global__ __launch_bounds__(256, 2)
void shared_gemm(const float* __restrict__ X, const float* __restrict__ W,
                 const float* __restrict__ bias, const float* __restrict__ p_ss,
                 const float* __restrict__ p_rs, float* __restrict__ out)
{
    const int mb = blockIdx.x * TILE_M;
    const int nb = blockIdx.y * TILE_N;
    gemm_tile<false>(X, W, bias, p_ss[0], 1.f + p_rs[0], out, mb, nb, BTOK, 0);
}

// ---------------- K3: expert grouped GEMM ----------------
__global__ __launch_bounds__(256, 2)
void expert_gemm(const float* __restrict__ X, const float* __restrict__ Wall,
                 const float* __restrict__ Ball, const float* __restrict__ p_rs,
                 float* __restrict__ out)
{
    const int e = blockIdx.z;
    const int cnt = g_cnt[e];
    const int mb = blockIdx.x * TILE_M;
    if (mb >= cnt) return;
    const int nb = blockIdx.y * TILE_N;
    const float* W    = Wall + (size_t)e * HIDDEN * HIDDEN;
    const float* bias = Ball + (size_t)e * HIDDEN;
    gemm_tile<true>(X, W, bias, p_rs[0], 0.f, out, mb, nb, cnt, e);
}

// ---------------- K4: gate loss ----------------
__global__ void loss_kernel(float* __restrict__ out, int out_size) {
    if (threadIdx.x == 0) {
        float acc = 0.f;
        #pragma unroll
        for (int e = 0; e < NEXP; e++) {
            float p = g_psum[e] * (1.f / (float)BTOK);
            float d = 0.125f - p;
            acc += d * d;
        }
        float loss = acc * (0.01f / 8.f);
        for (long long i = (long long)BTOK * HIDDEN; i < out_size; i++)
            out[i] = loss;
    }
}

// ---------------- launcher ----------------
extern "C" void kernel_launch(void* const* d_in, const int* in_sizes, int n_in,
                              void* d_out, int out_size) {
    const float* x      = (const float*)d_in[0];
    const float* noise  = (const float*)d_in[1];
    const float* gw1    = (const float*)d_in[2];
    const float* gb1    = (const float*)d_in[3];
    const float* gw2    = (const float*)d_in[4];
    const float* gb2    = (const float*)d_in[5];
    const float* sw     = (const float*)d_in[6];
    const float* sb     = (const float*)d_in[7];
    const float* sscale = (const float*)d_in[8];
    const float* ew     = (const float*)d_in[9];
    const float* eb     = (const float*)d_in[10];
    const float* rscale = (const float*)d_in[11];
    float* out = (float*)d_out;

    static bool attr_done = false;
    if (!attr_done) {
        cudaFuncSetAttribute(shared_gemm, cudaFuncAttributeMaxDynamicSharedMemorySize, SMEM_TOTAL);
        cudaFuncSetAttribute(expert_gemm, cudaFuncAttributeMaxDynamicSharedMemorySize, SMEM_TOTAL);
        attr_done = true;
    }

    init_kernel<<<1, 32>>>();
    gating_kernel<<<128, 256>>>(x, noise, gw1, gb1, gw2, gb2);
    shared_gemm<<<dim3(BTOK / TILE_M, HIDDEN / TILE_N), 256, SMEM_TOTAL>>>(
        x, sw, sb, sscale, rscale, out);
    expert_gemm<<<dim3(BTOK / TILE_M, HIDDEN / TILE_N, NEXP), 256, SMEM_TOTAL>>>(
        x, ew, eb, rscale, out);
    loss_kernel<<<1, 32>>>(out, out_size);
}

// round 6
// speedup vs baseline: 2.9246x; 1.0065x over previous
#include <cuda_runtime.h>
#include <cstdint>
#include <math.h>

#define HIDDEN 2048
#define NEXP 8
#define GDIM 64
#define BTOK 4096

#define TILE_M 128
#define TILE_N 128
#define BK 32
#define NCHUNKS (HIDDEN / BK)       // 64
#define NSTAGE 3

#define SA 36                        // A smem row stride (floats)
#define SB 136                       // B smem row stride (floats)
#define A_STAGE_BYTES (128 * SA * 4) // 18432
#define B_STAGE_BYTES (BK * SB * 4)  // 17408
#define STAGE_BYTES (A_STAGE_BYTES + B_STAGE_BYTES) // 35840
#define SMEM_HDR 1024
#define SMEM_TOTAL (SMEM_HDR + NSTAGE * STAGE_BYTES) // 108544 -> 2 CTAs/SM

// ---------------- device scratch ----------------
__device__ int   g_cnt[NEXP];
__device__ int   g_tok[NEXP][BTOK];
__device__ float g_wt[NEXP][BTOK];
__device__ float g_psum[NEXP];
__device__ float g_xp[(size_t)BTOK * HIDDEN];   // k-residue permuted X (32MB)

// ---------------- helpers ----------------
__device__ __forceinline__ uint32_t smem_u32(const void* p) {
    uint32_t a;
    asm("{ .reg .u64 t; cvta.to.shared.u64 t, %1; cvt.u32.u64 %0, t; }" : "=r"(a) : "l"(p));
    return a;
}
__device__ __forceinline__ void cp16(uint32_t dst, const void* src) {
    asm volatile("cp.async.cg.shared.global [%0], [%1], 16;" :: "r"(dst), "l"(src));
}
#define CP_COMMIT() asm volatile("cp.async.commit_group;" ::: "memory")
#define CP_WAIT(n)  asm volatile("cp.async.wait_group %0;" :: "n"(n) : "memory")

__device__ __forceinline__ void mma_tf32(float* d, uint32_t a0, uint32_t a1,
                                         uint32_t a2, uint32_t a3,
                                         uint32_t b0, uint32_t b1) {
    asm volatile(
        "mma.sync.aligned.m16n8k8.row.col.f32.tf32.tf32.f32 "
        "{%0,%1,%2,%3}, {%4,%5,%6,%7}, {%8,%9}, {%0,%1,%2,%3};"
        : "+f"(d[0]), "+f"(d[1]), "+f"(d[2]), "+f"(d[3])
        : "r"(a0), "r"(a1), "r"(a2), "r"(a3), "r"(b0), "r"(b1));
}
__device__ __forceinline__ void red_add_v2(float* p, float a, float b) {
    asm volatile("red.global.add.v2.f32 [%0], {%1, %2};" :: "l"(p), "f"(a), "f"(b) : "memory");
}
__device__ __forceinline__ float sigf(float z) { return 1.f / (1.f + __expf(-z)); }

// ---------------- K0: zero counters ----------------
__global__ void init_kernel() {
    int t = threadIdx.x;
    if (t < NEXP) { g_cnt[t] = 0; g_psum[t] = 0.f; }
}

// ---------------- K0b: k-residue permute of X + out base init ----------------
// Xp[tok][c*32 + (k%4)*8 + k/4] = X[tok][c*32 + k];  out = (1+rs)*x
__global__ __launch_bounds__(256) void permute_kernel(const float* __restrict__ X,
                                                      const float* __restrict__ p_rs,
                                                      float* __restrict__ out) {
    int t = blockIdx.x * 256 + threadIdx.x;      // one float4 of X
    int tok = t >> 9;                            // 512 float4 per token
    int q   = t & 511;
    int c   = q >> 3;                            // chunk 0..63
    int j   = q & 7;                             // quad index within chunk
    const float xscale = 1.f + p_rs[0];
    float4 v = *(const float4*)&X[(size_t)tok * HIDDEN + c * 32 + j * 4];
    float* dst = &g_xp[(size_t)tok * HIDDEN + c * 32 + j];
    dst[0]  = v.x;   // residue 0
    dst[8]  = v.y;   // residue 1
    dst[16] = v.z;   // residue 2
    dst[24] = v.w;   // residue 3
    float4 ov = make_float4(xscale * v.x, xscale * v.y, xscale * v.z, xscale * v.w);
    *(float4*)&out[(size_t)tok * HIDDEN + c * 32 + j * 4] = ov;
}

// ---------------- K1: gating ----------------
__global__ __launch_bounds__(256) void gating_kernel(
    const float* __restrict__ X, const float* __restrict__ noise,
    const float* __restrict__ gw1, const float* __restrict__ gb1,
    const float* __restrict__ gw2, const float* __restrict__ gb2)
{
    __shared__ float xs[32][68];
    __shared__ float hs[32][65];
    __shared__ float lg[32][NEXP];
    __shared__ float ws2[GDIM * NEXP];
    __shared__ float bs2[NEXP];

    const int tid  = threadIdx.x;
    const int tok0 = blockIdx.x * 32;
    const int j = tid & 63;
    const int r = tid >> 6;

    ws2[tid]       = gw2[tid];
    ws2[tid + 256] = gw2[tid + 256];
    if (tid < NEXP) bs2[tid] = gb2[tid];

    float acc[8];
    const float b1 = gb1[j];
    #pragma unroll
    for (int u = 0; u < 8; u++) acc[u] = b1;

    for (int k0 = 0; k0 < HIDDEN; k0 += 64) {
        __syncthreads();
        #pragma unroll
        for (int rr = 0; rr < 2; rr++) {
            int idx = tid + rr * 256;
            int row = idx >> 4, q = (idx & 15) << 2;
            float4 v = *(const float4*)&X[(size_t)(tok0 + row) * HIDDEN + k0 + q];
            *(float4*)&xs[row][q] = v;
        }
        __syncthreads();
        #pragma unroll 8
        for (int kk = 0; kk < 64; kk++) {
            float w = gw1[(size_t)(k0 + kk) * GDIM + j];
            #pragma unroll
            for (int u = 0; u < 8; u++) acc[u] = fmaf(xs[r + 4 * u][kk], w, acc[u]);
        }
    }
    #pragma unroll
    for (int u = 0; u < 8; u++) hs[r + 4 * u][j] = fmaxf(acc[u], 0.f);
    __syncthreads();

    {
        int lt = tid >> 3, e = tid & 7;
        float a = bs2[e];
        #pragma unroll 8
        for (int k = 0; k < GDIM; k++) a = fmaf(hs[lt][k], ws2[k * NEXP + e], a);
        lg[lt][e] = a;
    }
    __syncthreads();

    if (tid < 32) {
        int lt = tid;
        int token = tok0 + lt;
        float g[NEXP];
        float m = -1e30f;
        #pragma unroll
        for (int e = 0; e < NEXP; e++) { g[e] = lg[lt][e]; m = fmaxf(m, g[e]); }
        float s = 0.f;
        #pragma unroll
        for (int e = 0; e < NEXP; e++) { g[e] = expf(g[e] - m); s += g[e]; }
        float inv = 1.f / s;
        #pragma unroll
        for (int e = 0; e < NEXP; e++) {
            g[e] = g[e] * inv + noise[token * NEXP + e] * 0.01f;
            lg[lt][e] = g[e];
        }
        int i1 = 0; float v1 = g[0];
        #pragma unroll
        for (int e = 1; e < NEXP; e++) if (g[e] > v1) { v1 = g[e]; i1 = e; }
        int i2 = -1; float v2 = -1e30f;
        #pragma unroll
        for (int e = 0; e < NEXP; e++) if (e != i1 && g[e] > v2) { v2 = g[e]; i2 = e; }
        float wsum = v1 + v2;
        float w1 = v1 / wsum, w2 = v2 / wsum;
        int p1 = atomicAdd(&g_cnt[i1], 1);
        g_tok[i1][p1] = token; g_wt[i1][p1] = w1;
        int p2 = atomicAdd(&g_cnt[i2], 1);
        g_tok[i2][p2] = token; g_wt[i2][p2] = w2;
    }
    __syncthreads();
    if (tid < NEXP) {
        float s = 0.f;
        #pragma unroll
        for (int t = 0; t < 32; t++) s += lg[t][tid];
        atomicAdd(&g_psum[tid], s);
    }
}

// ---------------- stage loader (A from permuted Xp, B from W) ----------------
template<bool EXPERT>
__device__ __forceinline__ void load_stage(
    const float* __restrict__ W,
    int nb, int mb, const int* __restrict__ toks,
    uint32_t smem_base, int chunk, int buf, int tid)
{
    const uint32_t abase = smem_base + SMEM_HDR + buf * STAGE_BYTES;
    const uint32_t bbase = abase + A_STAGE_BYTES;
    const int k0 = chunk * BK;

    // A: 128 rows x 32 floats (residue-permuted in Xp)
    #pragma unroll
    for (int j = 0; j < 4; j++) {
        int idx = tid + j * 256;
        int row = idx >> 3, c = idx & 7;
        int tok = EXPERT ? toks[row] : (mb + row);
        cp16(abase + (uint32_t)(row * (SA * 4) + c * 16),
             &g_xp[(size_t)tok * HIDDEN + k0 + c * 4]);
    }
    // B: 32 k-rows x 128 n floats
    #pragma unroll
    for (int j = 0; j < 4; j++) {
        int idx = tid + j * 256;
        int row = idx >> 5, c = idx & 31;
        cp16(bbase + (uint32_t)(row * (SB * 4) + c * 16),
             W + (size_t)(k0 + row) * HIDDEN + nb + c * 4);
    }
    CP_COMMIT();
}

// ---------------- GEMM tile body ----------------
template<bool EXPERT>
__device__ __forceinline__ void gemm_tile(
    const float* __restrict__ W,
    const float* __restrict__ bias, float sc1,
    float* __restrict__ out, int mb, int nb, int cnt, int e)
{
    extern __shared__ char smem[];
    const uint32_t smem_base = smem_u32(smem);
    const int tid = threadIdx.x;
    const int wid = tid >> 5;
    const int lane = tid & 31;
    const int wm = wid & 1;          // M half
    const int wn = wid >> 1;         // N quarter

    int*   toks = (int*)smem;
    float* wts  = (float*)(smem + 512);

    if (EXPERT) {
        if (tid < 128) {
            int li = mb + tid;
            toks[tid] = (li < cnt) ? g_tok[e][li] : 0;
            wts[tid]  = (li < cnt) ? g_wt[e][li] : 0.f;
        }
        __syncthreads();
    }

    float acc[4][4][4];
    #pragma unroll
    for (int mt = 0; mt < 4; mt++)
        #pragma unroll
        for (int nt = 0; nt < 4; nt++)
            #pragma unroll
            for (int q = 0; q < 4; q++) acc[mt][nt][q] = 0.f;

    load_stage<EXPERT>(W, nb, mb, toks, smem_base, 0, 0, tid);
    load_stage<EXPERT>(W, nb, mb, toks, smem_base, 1, 1, tid);

    const int lq = lane >> 2;   // 0..7
    const int lr = lane & 3;    // 0..3

    for (int i = 0; i < NCHUNKS; i++) {
        const int buf = i % NSTAGE;
        CP_WAIT(1);
        __syncthreads();

        if (i + 2 < NCHUNKS)
            load_stage<EXPERT>(W, nb, mb, toks, smem_base, i + 2, (i + 2) % NSTAGE, tid);
        else
            CP_COMMIT();   // keep group arithmetic invariant

        const float* As = (const float*)(smem + SMEM_HDR + buf * STAGE_BYTES);
        const float* Bs = (const float*)(smem + SMEM_HDR + buf * STAGE_BYTES + A_STAGE_BYTES);

        // two ks-pair passes: 16 B regs live, one LDS.128 pair per mt
        #pragma unroll
        for (int ksp = 0; ksp < 2; ksp++) {
            uint32_t bf[2][4][2];
            #pragma unroll
            for (int kh = 0; kh < 2; kh++) {
                int kk = (ksp * 2 + kh) * 8 + lr;
                #pragma unroll
                for (int nt = 0; nt < 4; nt++) {
                    int nn = wn * 32 + nt * 8 + lq;
                    bf[kh][nt][0] = __float_as_uint(Bs[kk * SB + nn]);
                    bf[kh][nt][1] = __float_as_uint(Bs[(kk + 4) * SB + nn]);
                }
            }
            #pragma unroll
            for (int mt = 0; mt < 4; mt++) {
                int r0 = wm * 64 + mt * 16 + lq;
                float4 alo = *(const float4*)&As[r0 * SA + lr * 8 + ksp * 4];
                float4 ahi = *(const float4*)&As[(r0 + 8) * SA + lr * 8 + ksp * 4];
                #pragma unroll
                for (int nt = 0; nt < 4; nt++) {
                    mma_tf32(acc[mt][nt],
                             __float_as_uint(alo.x), __float_as_uint(ahi.x),
                             __float_as_uint(alo.y), __float_as_uint(ahi.y),
                             bf[0][nt][0], bf[0][nt][1]);
                    mma_tf32(acc[mt][nt],
                             __float_as_uint(alo.z), __float_as_uint(ahi.z),
                             __float_as_uint(alo.w), __float_as_uint(ahi.w),
                             bf[1][nt][0], bf[1][nt][1]);
                }
            }
        }
    }

    // ---------------- epilogue: out already holds (1+rs)*x; add contribution ----------------
    #pragma unroll
    for (int mt = 0; mt < 4; mt++) {
        #pragma unroll
        for (int h = 0; h < 2; h++) {
            int mrow = wm * 64 + mt * 16 + lq + h * 8;
            int token;
            float wscale;
            if (EXPERT) {
                if (mb + mrow >= cnt) continue;
                token = toks[mrow];
                wscale = sc1 * wts[mrow];
            } else {
                token = mb + mrow;
                wscale = sc1;
            }
            float* orow = out + (size_t)token * HIDDEN;
            #pragma unroll
            for (int nt = 0; nt < 4; nt++) {
                int col = nb + wn * 32 + nt * 8 + 2 * lr;
                float2 bv = *(const float2*)&bias[col];
                float s0 = wscale * sigf(acc[mt][nt][2 * h]     + bv.x);
                float s1 = wscale * sigf(acc[mt][nt][2 * h + 1] + bv.y);
                red_add_v2(orow + col, s0, s1);
            }
        }
    }
}

// ---------------- K2: fused shared + expert GEMM (z=0..7 experts, z=8 shared) ----------------
__global__ __launch_bounds__(256, 2)
void fused_gemm(const float* __restrict__ SW, const float* __restrict__ SBias,
                const float* __restrict__ p_ss,
                const float* __restrict__ EW, const float* __restrict__ EBias,
                const float* __restrict__ p_rs,
                float* __restrict__ out)
{
    const int nb = blockIdx.y * TILE_N;
    const int mb = blockIdx.x * TILE_M;
    if (blockIdx.z == NEXP) {
        gemm_tile<false>(SW, SBias, p_ss[0], out, mb, nb, BTOK, 0);
    } else {
        const int e = blockIdx.z;
        const int cnt = g_cnt[e];
        if (mb >= cnt) return;
        gemm_tile<true>(EW + (size_t)e * HIDDEN * HIDDEN,
                        EBias + (size_t)e * HIDDEN, p_rs[0], out, mb, nb, cnt, e);
    }
}

// ---------------- K4: gate loss ----------------
__global__ void loss_kernel(float* __restrict__ out, int out_size) {
    if (threadIdx.x == 0) {
        float acc = 0.f;
        #pragma unroll
        for (int e = 0; e < NEXP; e++) {
            float p = g_psum[e] * (1.f / (float)BTOK);
            float d = 0.125f - p;
            acc += d * d;
        }
        float loss = acc * (0.01f / 8.f);
        for (long long i = (long long)BTOK * HIDDEN; i < out_size; i++)
            out[i] = loss;
    }
}

// ---------------- launcher ----------------
extern "C" void kernel_launch(void* const* d_in, const int* in_sizes, int n_in,
                              void* d_out, int out_size) {
    const float* x      = (const float*)d_in[0];
    const float* noise  = (const float*)d_in[1];
    const float* gw1    = (const float*)d_in[2];
    const float* gb1    = (const float*)d_in[3];
    const float* gw2    = (const float*)d_in[4];
    const float* gb2    = (const float*)d_in[5];
    const float* sw     = (const float*)d_in[6];
    const float* sb     = (const float*)d_in[7];
    const float* sscale = (const float*)d_in[8];
    const float* ew     = (const float*)d_in[9];
    const float* eb     = (const float*)d_in[10];
    const float* rscale = (const float*)d_in[11];
    float* out = (float*)d_out;

    static bool attr_done = false;
    if (!attr_done) {
        cudaFuncSetAttribute(fused_gemm, cudaFuncAttributeMaxDynamicSharedMemorySize, SMEM_TOTAL);
        attr_done = true;
    }

    init_kernel<<<1, 32>>>();
    permute_kernel<<<(BTOK * HIDDEN / 4) / 256, 256>>>(x, rscale, out);
    gating_kernel<<<128, 256>>>(x, noise, gw1, gb1, gw2, gb2);
    fused_gemm<<<dim3(BTOK / TILE_M, HIDDEN / TILE_N, NEXP + 1), 256, SMEM_TOTAL>>>(
        sw, sb, sscale, ew, eb, rscale, out);
    loss_kernel<<<1, 32>>>(out, out_size);
}

// round 7
// speedup vs baseline: 4.4700x; 1.5284x over previous
#include <cuda_runtime.h>
#include <cuda_bf16.h>
#include <cstdint>
#include <math.h>

#define HIDDEN 2048
#define NEXP 8
#define GDIM 64
#define BTOK 4096

#define TILE_M 128
#define TILE_N 128
#define BK 32
#define NCHUNKS (HIDDEN / BK)       // 64
#define NSTAGE 4

// bf16 smem tiles
#define A_ROW_B 80                   // 32 bf16 (64B) + 16B pad  -> conflict-free LDSM
#define B_ROW_B 272                  // 128 bf16 (256B) + 16B pad -> conflict-free LDSM.trans
#define A_STAGE_BYTES (128 * A_ROW_B)  // 10240
#define B_STAGE_BYTES (BK * B_ROW_B)   // 8704
#define STAGE_BYTES (A_STAGE_BYTES + B_STAGE_BYTES) // 18944
#define SMEM_HDR 1024
#define SMEM_TOTAL (SMEM_HDR + NSTAGE * STAGE_BYTES) // 76800 -> 2 CTAs/SM

// ---------------- device scratch ----------------
__device__ int   g_cnt[NEXP];
__device__ int   g_tok[NEXP][BTOK];
__device__ float g_wt[NEXP][BTOK];
__device__ float g_psum[NEXP];
__device__ uint16_t g_xa[(size_t)BTOK * HIDDEN];          // bf16 X (16MB)
__device__ uint16_t g_wb[(size_t)(NEXP + 1) * HIDDEN * HIDDEN]; // bf16 W: 0..7 experts, 8 shared (75.5MB)

// ---------------- helpers ----------------
__device__ __forceinline__ uint32_t smem_u32(const void* p) {
    uint32_t a;
    asm("{ .reg .u64 t; cvta.to.shared.u64 t, %1; cvt.u32.u64 %0, t; }" : "=r"(a) : "l"(p));
    return a;
}
__device__ __forceinline__ void cp16(uint32_t dst, const void* src) {
    asm volatile("cp.async.cg.shared.global [%0], [%1], 16;" :: "r"(dst), "l"(src));
}
#define CP_COMMIT() asm volatile("cp.async.commit_group;" ::: "memory")
#define CP_WAIT(n)  asm volatile("cp.async.wait_group %0;" :: "n"(n) : "memory")

__device__ __forceinline__ void ldsm_x4(uint32_t* r, uint32_t addr) {
    asm volatile("ldmatrix.sync.aligned.m8n8.x4.shared.b16 {%0,%1,%2,%3}, [%4];"
        : "=r"(r[0]), "=r"(r[1]), "=r"(r[2]), "=r"(r[3]) : "r"(addr));
}
__device__ __forceinline__ void ldsm_x4_t(uint32_t* r, uint32_t addr) {
    asm volatile("ldmatrix.sync.aligned.m8n8.x4.trans.shared.b16 {%0,%1,%2,%3}, [%4];"
        : "=r"(r[0]), "=r"(r[1]), "=r"(r[2]), "=r"(r[3]) : "r"(addr));
}
__device__ __forceinline__ void mma_bf16(float* d, const uint32_t* a, uint32_t b0, uint32_t b1) {
    asm volatile(
        "mma.sync.aligned.m16n8k16.row.col.f32.bf16.bf16.f32 "
        "{%0,%1,%2,%3}, {%4,%5,%6,%7}, {%8,%9}, {%0,%1,%2,%3};"
        : "+f"(d[0]), "+f"(d[1]), "+f"(d[2]), "+f"(d[3])
        : "r"(a[0]), "r"(a[1]), "r"(a[2]), "r"(a[3]), "r"(b0), "r"(b1));
}
__device__ __forceinline__ uint32_t pack_bf16(float lo, float hi) {
    uint32_t r;
    asm("cvt.rn.bf16x2.f32 %0, %1, %2;" : "=r"(r) : "f"(hi), "f"(lo));  // op1->high half
    return r;
}
__device__ __forceinline__ void red_add_v2(float* p, float a, float b) {
    asm volatile("red.global.add.v2.f32 [%0], {%1, %2};" :: "l"(p), "f"(a), "f"(b) : "memory");
}
__device__ __forceinline__ float sigf(float z) { return 1.f / (1.f + __expf(-z)); }

// ---------------- K0: zero counters ----------------
__global__ void init_kernel() {
    int t = threadIdx.x;
    if (t < NEXP) { g_cnt[t] = 0; g_psum[t] = 0.f; }
}

// ---------------- K0a: X -> bf16 + out base init ----------------
__global__ __launch_bounds__(256) void convert_x(const float* __restrict__ X,
                                                 const float* __restrict__ p_rs,
                                                 float* __restrict__ out) {
    size_t t = (size_t)blockIdx.x * 256 + threadIdx.x;  // one float4
    float4 v = ((const float4*)X)[t];
    uint2 p;
    p.x = pack_bf16(v.x, v.y);
    p.y = pack_bf16(v.z, v.w);
    ((uint2*)g_xa)[t] = p;
    const float s = 1.f + p_rs[0];
    ((float4*)out)[t] = make_float4(s * v.x, s * v.y, s * v.z, s * v.w);
}

// ---------------- K0b: W (experts + shared) -> bf16 ----------------
__global__ __launch_bounds__(256) void convert_w(const float* __restrict__ EW,
                                                 const float* __restrict__ SW) {
    size_t t = (size_t)blockIdx.x * 256 + threadIdx.x;  // one float4
    size_t elem = t * 4;
    const size_t EXP_ELEMS = (size_t)NEXP * HIDDEN * HIDDEN;  // 33554432
    float4 v = (elem < EXP_ELEMS) ? ((const float4*)EW)[t]
                                  : *(const float4*)(SW + (elem - EXP_ELEMS));
    uint2 p;
    p.x = pack_bf16(v.x, v.y);
    p.y = pack_bf16(v.z, v.w);
    ((uint2*)g_wb)[t] = p;
}

// ---------------- K1: gating ----------------
__global__ __launch_bounds__(256) void gating_kernel(
    const float* __restrict__ X, const float* __restrict__ noise,
    const float* __restrict__ gw1, const float* __restrict__ gb1,
    const float* __restrict__ gw2, const float* __restrict__ gb2)
{
    __shared__ float xs[32][68];
    __shared__ float hs[32][65];
    __shared__ float lg[32][NEXP];
    __shared__ float ws2[GDIM * NEXP];
    __shared__ float bs2[NEXP];

    const int tid  = threadIdx.x;
    const int tok0 = blockIdx.x * 32;
    const int j = tid & 63;
    const int r = tid >> 6;

    ws2[tid]       = gw2[tid];
    ws2[tid + 256] = gw2[tid + 256];
    if (tid < NEXP) bs2[tid] = gb2[tid];

    float acc[8];
    const float b1 = gb1[j];
    #pragma unroll
    for (int u = 0; u < 8; u++) acc[u] = b1;

    for (int k0 = 0; k0 < HIDDEN; k0 += 64) {
        __syncthreads();
        #pragma unroll
        for (int rr = 0; rr < 2; rr++) {
            int idx = tid + rr * 256;
            int row = idx >> 4, q = (idx & 15) << 2;
            float4 v = *(const float4*)&X[(size_t)(tok0 + row) * HIDDEN + k0 + q];
            *(float4*)&xs[row][q] = v;
        }
        __syncthreads();
        #pragma unroll 8
        for (int kk = 0; kk < 64; kk++) {
            float w = gw1[(size_t)(k0 + kk) * GDIM + j];
            #pragma unroll
            for (int u = 0; u < 8; u++) acc[u] = fmaf(xs[r + 4 * u][kk], w, acc[u]);
        }
    }
    #pragma unroll
    for (int u = 0; u < 8; u++) hs[r + 4 * u][j] = fmaxf(acc[u], 0.f);
    __syncthreads();

    {
        int lt = tid >> 3, e = tid & 7;
        float a = bs2[e];
        #pragma unroll 8
        for (int k = 0; k < GDIM; k++) a = fmaf(hs[lt][k], ws2[k * NEXP + e], a);
        lg[lt][e] = a;
    }
    __syncthreads();

    if (tid < 32) {
        int lt = tid;
        int token = tok0 + lt;
        float g[NEXP];
        float m = -1e30f;
        #pragma unroll
        for (int e = 0; e < NEXP; e++) { g[e] = lg[lt][e]; m = fmaxf(m, g[e]); }
        float s = 0.f;
        #pragma unroll
        for (int e = 0; e < NEXP; e++) { g[e] = expf(g[e] - m); s += g[e]; }
        float inv = 1.f / s;
        #pragma unroll
        for (int e = 0; e < NEXP; e++) {
            g[e] = g[e] * inv + noise[token * NEXP + e] * 0.01f;
            lg[lt][e] = g[e];
        }
        int i1 = 0; float v1 = g[0];
        #pragma unroll
        for (int e = 1; e < NEXP; e++) if (g[e] > v1) { v1 = g[e]; i1 = e; }
        int i2 = -1; float v2 = -1e30f;
        #pragma unroll
        for (int e = 0; e < NEXP; e++) if (e != i1 && g[e] > v2) { v2 = g[e]; i2 = e; }
        float wsum = v1 + v2;
        float w1 = v1 / wsum, w2 = v2 / wsum;
        int p1 = atomicAdd(&g_cnt[i1], 1);
        g_tok[i1][p1] = token; g_wt[i1][p1] = w1;
        int p2 = atomicAdd(&g_cnt[i2], 1);
        g_tok[i2][p2] = token; g_wt[i2][p2] = w2;
    }
    __syncthreads();
    if (tid < NEXP) {
        float s = 0.f;
        #pragma unroll
        for (int t = 0; t < 32; t++) s += lg[t][tid];
        atomicAdd(&g_psum[tid], s);
    }
}

// ---------------- stage loader (bf16 tiles) ----------------
template<bool EXPERT>
__device__ __forceinline__ void load_stage(
    const uint16_t* __restrict__ Wb,
    int nb, int mb, const int* __restrict__ toks,
    uint32_t smem_base, int chunk, int buf, int tid)
{
    const uint32_t abase = smem_base + SMEM_HDR + buf * STAGE_BYTES;
    const uint32_t bbase = abase + A_STAGE_BYTES;
    const int k0 = chunk * BK;

    // A: 128 rows x 32 bf16 (4x16B per row)
    #pragma unroll
    for (int j = 0; j < 2; j++) {
        int idx = tid + j * 256;
        int row = idx >> 2, c = idx & 3;
        int tok = EXPERT ? toks[row] : (mb + row);
        cp16(abase + (uint32_t)(row * A_ROW_B + c * 16),
             g_xa + (size_t)tok * HIDDEN + k0 + c * 8);
    }
    // B: 32 k-rows x 128 n bf16 (16x16B per row)
    #pragma unroll
    for (int j = 0; j < 2; j++) {
        int idx = tid + j * 256;
        int row = idx >> 4, c = idx & 15;
        cp16(bbase + (uint32_t)(row * B_ROW_B + c * 16),
             Wb + (size_t)(k0 + row) * HIDDEN + nb + c * 8);
    }
    CP_COMMIT();
}

// ---------------- GEMM tile body (bf16 mma.sync m16n8k16 + ldmatrix) ----------------
template<bool EXPERT>
__device__ __forceinline__ void gemm_tile(
    const uint16_t* __restrict__ Wb,
    const float* __restrict__ bias, float sc1,
    float* __restrict__ out, int mb, int nb, int cnt, int e)
{
    extern __shared__ char smem[];
    const uint32_t smem_base = smem_u32(smem);
    const int tid = threadIdx.x;
    const int wid = tid >> 5;
    const int lane = tid & 31;
    const int wm = wid & 1;          // M half (64 rows)
    const int wn = wid >> 1;         // N quarter (32 cols)

    int*   toks = (int*)smem;
    float* wts  = (float*)(smem + 512);

    if (EXPERT) {
        if (tid < 128) {
            int li = mb + tid;
            toks[tid] = (li < cnt) ? g_tok[e][li] : 0;
            wts[tid]  = (li < cnt) ? g_wt[e][li] : 0.f;
        }
        __syncthreads();
    }

    float acc[4][4][4];
    #pragma unroll
    for (int mt = 0; mt < 4; mt++)
        #pragma unroll
        for (int nt = 0; nt < 4; nt++)
            #pragma unroll
            for (int q = 0; q < 4; q++) acc[mt][nt][q] = 0.f;

    // prologue: 3 stages in flight
    load_stage<EXPERT>(Wb, nb, mb, toks, smem_base, 0, 0, tid);
    load_stage<EXPERT>(Wb, nb, mb, toks, smem_base, 1, 1, tid);
    load_stage<EXPERT>(Wb, nb, mb, toks, smem_base, 2, 2, tid);

    // per-lane LDSM base offsets (loop-invariant)
    const uint32_t a_warp = (uint32_t)((lane & 15) * A_ROW_B + (lane >> 4) * 16 + wm * 64 * A_ROW_B);
    const uint32_t b_warp = (uint32_t)((lane & 15) * B_ROW_B + (lane >> 4) * 16 + wn * 64);

    for (int i0 = 0; i0 < NCHUNKS; i0 += 4) {
        #pragma unroll
        for (int u = 0; u < 4; u++) {
            const int i = i0 + u;                    // buf = u (compile-time)
            CP_WAIT(2);
            __syncthreads();

            if (i + 3 < NCHUNKS)
                load_stage<EXPERT>(Wb, nb, mb, toks, smem_base, i + 3, (u + 3) & 3, tid);
            else
                CP_COMMIT();

            const uint32_t ab = smem_base + SMEM_HDR + u * STAGE_BYTES + a_warp;
            const uint32_t bb = smem_base + SMEM_HDR + u * STAGE_BYTES + A_STAGE_BYTES + b_warp;

            #pragma unroll
            for (int ks = 0; ks < 2; ks++) {
                uint32_t af[4][4], bfr[2][4];
                #pragma unroll
                for (int mt = 0; mt < 4; mt++)
                    ldsm_x4(af[mt], ab + mt * (16 * A_ROW_B) + ks * 32);
                #pragma unroll
                for (int ng = 0; ng < 2; ng++)
                    ldsm_x4_t(bfr[ng], bb + ks * (16 * B_ROW_B) + ng * 32);
                #pragma unroll
                for (int mt = 0; mt < 4; mt++)
                    #pragma unroll
                    for (int ng = 0; ng < 2; ng++) {
                        mma_bf16(acc[mt][ng * 2 + 0], af[mt], bfr[ng][0], bfr[ng][1]);
                        mma_bf16(acc[mt][ng * 2 + 1], af[mt], bfr[ng][2], bfr[ng][3]);
                    }
            }
        }
    }

    // ---------------- epilogue: out holds (1+rs)*x; red.add contributions ----------------
    const int lq = lane >> 2;
    const int lr = lane & 3;
    #pragma unroll
    for (int mt = 0; mt < 4; mt++) {
        #pragma unroll
        for (int h = 0; h < 2; h++) {
            int mrow = wm * 64 + mt * 16 + lq + h * 8;
            int token;
            float wscale;
            if (EXPERT) {
                if (mb + mrow >= cnt) continue;
                token = toks[mrow];
                wscale = sc1 * wts[mrow];
            } else {
                token = mb + mrow;
                wscale = sc1;
            }
            float* orow = out + (size_t)token * HIDDEN;
            #pragma unroll
            for (int nt = 0; nt < 4; nt++) {
                int col = nb + wn * 32 + nt * 8 + 2 * lr;
                float2 bv = *(const float2*)&bias[col];
                float s0 = wscale * sigf(acc[mt][nt][2 * h]     + bv.x);
                float s1 = wscale * sigf(acc[mt][nt][2 * h + 1] + bv.y);
                red_add_v2(orow + col, s0, s1);
            }
        }
    }
}

// ---------------- K2: fused shared + expert GEMM (z=0..7 experts, z=8 shared) ----------------
__global__ __launch_bounds__(256, 2)
void fused_gemm(const float* __restrict__ SBias, const float* __restrict__ p_ss,
                const float* __restrict__ EBias, const float* __restrict__ p_rs,
                float* __restrict__ out)
{
    const int nb = blockIdx.y * TILE_N;
    const int mb = blockIdx.x * TILE_M;
    if (blockIdx.z == NEXP) {
        gemm_tile<false>(g_wb + (size_t)NEXP * HIDDEN * HIDDEN, SBias, p_ss[0],
                         out, mb, nb, BTOK, 0);
    } else {
        const int e = blockIdx.z;
        const int cnt = g_cnt[e];
        if (mb >= cnt) return;
        gemm_tile<true>(g_wb + (size_t)e * HIDDEN * HIDDEN,
                        EBias + (size_t)e * HIDDEN, p_rs[0], out, mb, nb, cnt, e);
    }
}

// ---------------- K4: gate loss ----------------
__global__ void loss_kernel(float* __restrict__ out, int out_size) {
    if (threadIdx.x == 0) {
        float acc = 0.f;
        #pragma unroll
        for (int e = 0; e < NEXP; e++) {
            float p = g_psum[e] * (1.f / (float)BTOK);
            float d = 0.125f - p;
            acc += d * d;
        }
        float loss = acc * (0.01f / 8.f);
        for (long long i = (long long)BTOK * HIDDEN; i < out_size; i++)
            out[i] = loss;
    }
}

// ---------------- launcher ----------------
extern "C" void kernel_launch(void* const* d_in, const int* in_sizes, int n_in,
                              void* d_out, int out_size) {
    const float* x      = (const float*)d_in[0];
    const float* noise  = (const float*)d_in[1];
    const float* gw1    = (const float*)d_in[2];
    const float* gb1    = (const float*)d_in[3];
    const float* gw2    = (const float*)d_in[4];
    const float* gb2    = (const float*)d_in[5];
    const float* sw     = (const float*)d_in[6];
    const float* sb     = (const float*)d_in[7];
    const float* sscale = (const float*)d_in[8];
    const float* ew     = (const float*)d_in[9];
    const float* eb     = (const float*)d_in[10];
    const float* rscale = (const float*)d_in[11];
    float* out = (float*)d_out;

    static bool attr_done = false;
    if (!attr_done) {
        cudaFuncSetAttribute(fused_gemm, cudaFuncAttributeMaxDynamicSharedMemorySize, SMEM_TOTAL);
        attr_done = true;
    }

    init_kernel<<<1, 32>>>();
    convert_x<<<(BTOK * HIDDEN / 4) / 256, 256>>>(x, rscale, out);
    convert_w<<<((NEXP + 1) * (HIDDEN * HIDDEN / 4)) / 256, 256>>>(ew, sw);
    gating_kernel<<<128, 256>>>(x, noise, gw1, gb1, gw2, gb2);
    fused_gemm<<<dim3(BTOK / TILE_M, HIDDEN / TILE_N, NEXP + 1), 256, SMEM_TOTAL>>>(
        sb, sscale, eb, rscale, out);
    loss_kernel<<<1, 32>>>(out, out_size);
}

// round 8
// speedup vs baseline: 6.4499x; 1.4429x over previous
#include <cuda_runtime.h>
#include <cuda_bf16.h>
#include <cstdint>
#include <math.h>

#define HIDDEN 2048
#define NEXP 8
#define GDIM 64
#define BTOK 4096

#define TILE_M 128
#define TILE_N 128
#define BK 32
#define NCHUNKS (HIDDEN / BK)       // 64
#define NSTAGE 4

// bf16 smem tiles
#define A_ROW_B 80                   // 32 bf16 (64B) + 16B pad  -> conflict-free LDSM
#define B_ROW_B 272                  // 128 bf16 (256B) + 16B pad -> conflict-free LDSM.trans
#define A_STAGE_BYTES (128 * A_ROW_B)  // 10240
#define B_STAGE_BYTES (BK * B_ROW_B)   // 8704
#define STAGE_BYTES (A_STAGE_BYTES + B_STAGE_BYTES) // 18944
#define SMEM_HDR 1024
#define SMEM_TOTAL (SMEM_HDR + NSTAGE * STAGE_BYTES) // 76800 -> 2 CTAs/SM

// ---------------- device scratch ----------------
__device__ int   g_cnt[NEXP];
__device__ int   g_tok[NEXP][BTOK];
__device__ float g_wt[NEXP][BTOK];
__device__ float g_psum[NEXP];
__device__ uint16_t g_xa[(size_t)BTOK * HIDDEN];          // bf16 X (16MB)
__device__ uint16_t g_wb[(size_t)(NEXP + 1) * HIDDEN * HIDDEN]; // bf16 W: 0..7 experts, 8 shared

// ---------------- helpers ----------------
__device__ __forceinline__ uint32_t smem_u32(const void* p) {
    uint32_t a;
    asm("{ .reg .u64 t; cvta.to.shared.u64 t, %1; cvt.u32.u64 %0, t; }" : "=r"(a) : "l"(p));
    return a;
}
__device__ __forceinline__ void cp16(uint32_t dst, const void* src) {
    asm volatile("cp.async.cg.shared.global [%0], [%1], 16;" :: "r"(dst), "l"(src));
}
#define CP_COMMIT() asm volatile("cp.async.commit_group;" ::: "memory")
#define CP_WAIT(n)  asm volatile("cp.async.wait_group %0;" :: "n"(n) : "memory")

__device__ __forceinline__ void ldsm_x4(uint32_t* r, uint32_t addr) {
    asm volatile("ldmatrix.sync.aligned.m8n8.x4.shared.b16 {%0,%1,%2,%3}, [%4];"
        : "=r"(r[0]), "=r"(r[1]), "=r"(r[2]), "=r"(r[3]) : "r"(addr));
}
__device__ __forceinline__ void ldsm_x4_t(uint32_t* r, uint32_t addr) {
    asm volatile("ldmatrix.sync.aligned.m8n8.x4.trans.shared.b16 {%0,%1,%2,%3}, [%4];"
        : "=r"(r[0]), "=r"(r[1]), "=r"(r[2]), "=r"(r[3]) : "r"(addr));
}
__device__ __forceinline__ void mma_bf16(float* d, const uint32_t* a, uint32_t b0, uint32_t b1) {
    asm volatile(
        "mma.sync.aligned.m16n8k16.row.col.f32.bf16.bf16.f32 "
        "{%0,%1,%2,%3}, {%4,%5,%6,%7}, {%8,%9}, {%0,%1,%2,%3};"
        : "+f"(d[0]), "+f"(d[1]), "+f"(d[2]), "+f"(d[3])
        : "r"(a[0]), "r"(a[1]), "r"(a[2]), "r"(a[3]), "r"(b0), "r"(b1));
}
__device__ __forceinline__ uint32_t pack_bf16(float lo, float hi) {
    uint32_t r;
    asm("cvt.rn.bf16x2.f32 %0, %1, %2;" : "=r"(r) : "f"(hi), "f"(lo));
    return r;
}
__device__ __forceinline__ void red_add_v2(float* p, float a, float b) {
    asm volatile("red.global.add.v2.f32 [%0], {%1, %2};" :: "l"(p), "f"(a), "f"(b) : "memory");
}
__device__ __forceinline__ float sigf(float z) { return 1.f / (1.f + __expf(-z)); }

// ---------------- K0: zero counters ----------------
__global__ void init_kernel() {
    int t = threadIdx.x;
    if (t < NEXP) { g_cnt[t] = 0; g_psum[t] = 0.f; }
}

// ---------------- K0a: X -> bf16 + out base init ----------------
__global__ __launch_bounds__(256) void convert_x(const float* __restrict__ X,
                                                 const float* __restrict__ p_rs,
                                                 float* __restrict__ out) {
    size_t t = (size_t)blockIdx.x * 256 + threadIdx.x;
    float4 v = ((const float4*)X)[t];
    uint2 p;
    p.x = pack_bf16(v.x, v.y);
    p.y = pack_bf16(v.z, v.w);
    ((uint2*)g_xa)[t] = p;
    const float s = 1.f + p_rs[0];
    ((float4*)out)[t] = make_float4(s * v.x, s * v.y, s * v.z, s * v.w);
}

// ---------------- K0b: W (experts + shared) -> bf16 ----------------
__global__ __launch_bounds__(256) void convert_w(const float* __restrict__ EW,
                                                 const float* __restrict__ SW) {
    size_t t = (size_t)blockIdx.x * 256 + threadIdx.x;
    size_t elem = t * 4;
    const size_t EXP_ELEMS = (size_t)NEXP * HIDDEN * HIDDEN;
    float4 v = (elem < EXP_ELEMS) ? ((const float4*)EW)[t]
                                  : *(const float4*)(SW + (elem - EXP_ELEMS));
    uint2 p;
    p.x = pack_bf16(v.x, v.y);
    p.y = pack_bf16(v.z, v.w);
    ((uint2*)g_wb)[t] = p;
}

// ---------------- K1: gating (smem-staged, cp.async double-buffered) ----------------
#define GK 32   // k-chunk
__global__ __launch_bounds__(256) void gating_kernel(
    const float* __restrict__ X, const float* __restrict__ noise,
    const float* __restrict__ gw1, const float* __restrict__ gb1,
    const float* __restrict__ gw2, const float* __restrict__ gb2)
{
    __shared__ float xs[2][32][36];   // 32 tokens x 32 k (pad 36)
    __shared__ float ws[2][GK][68];   // 32 k x 64 j (pad 68)
    __shared__ float hs[32][65];
    __shared__ float lg[32][NEXP];
    __shared__ float ws2[GDIM * NEXP];
    __shared__ float bs2[NEXP];

    const int tid  = threadIdx.x;
    const int tok0 = blockIdx.x * 32;
    const int j = tid & 63;
    const int r = tid >> 6;

    const uint32_t xs_b = smem_u32(&xs[0][0][0]);
    const uint32_t ws_b = smem_u32(&ws[0][0][0]);

    ws2[tid]       = gw2[tid];
    ws2[tid + 256] = gw2[tid + 256];
    if (tid < NEXP) bs2[tid] = gb2[tid];

    // cp.async stage loader: chunk c into buf b
    auto stage = [&](int c, int b) {
        int k0 = c * GK;
        {   // X: 32 rows x 32 floats -> 256 cp16, 1 per thread
            int row = tid >> 3, q = tid & 7;
            cp16(xs_b + (uint32_t)(b * 32 * 36 * 4 + row * 36 * 4 + q * 16),
                 &X[(size_t)(tok0 + row) * HIDDEN + k0 + q * 4]);
        }
        {   // W: 32 rows x 64 floats -> 512 cp16, 2 per thread
            #pragma unroll
            for (int jj = 0; jj < 2; jj++) {
                int idx = tid + jj * 256;
                int row = idx >> 4, q = idx & 15;
                cp16(ws_b + (uint32_t)(b * GK * 68 * 4 + row * 68 * 4 + q * 16),
                     &gw1[(size_t)(k0 + row) * GDIM + q * 4]);
            }
        }
        CP_COMMIT();
    };

    float acc[8];
    const float b1 = gb1[j];
    #pragma unroll
    for (int u = 0; u < 8; u++) acc[u] = b1;

    stage(0, 0);
    for (int c = 0; c < HIDDEN / GK; c++) {
        const int buf = c & 1;
        if (c + 1 < HIDDEN / GK) stage(c + 1, (c + 1) & 1);
        else CP_COMMIT();
        CP_WAIT(1);
        __syncthreads();
        #pragma unroll 8
        for (int kk = 0; kk < GK; kk++) {
            float w = ws[buf][kk][j];
            #pragma unroll
            for (int u = 0; u < 8; u++) acc[u] = fmaf(xs[buf][r + 4 * u][kk], w, acc[u]);
        }
        __syncthreads();
    }
    #pragma unroll
    for (int u = 0; u < 8; u++) hs[r + 4 * u][j] = fmaxf(acc[u], 0.f);
    __syncthreads();

    {
        int lt = tid >> 3, e = tid & 7;
        float a = bs2[e];
        #pragma unroll 8
        for (int k = 0; k < GDIM; k++) a = fmaf(hs[lt][k], ws2[k * NEXP + e], a);
        lg[lt][e] = a;
    }
    __syncthreads();

    if (tid < 32) {
        int lt = tid;
        int token = tok0 + lt;
        float g[NEXP];
        float m = -1e30f;
        #pragma unroll
        for (int e = 0; e < NEXP; e++) { g[e] = lg[lt][e]; m = fmaxf(m, g[e]); }
        float s = 0.f;
        #pragma unroll
        for (int e = 0; e < NEXP; e++) { g[e] = expf(g[e] - m); s += g[e]; }
        float inv = 1.f / s;
        #pragma unroll
        for (int e = 0; e < NEXP; e++) {
            g[e] = g[e] * inv + noise[token * NEXP + e] * 0.01f;
            lg[lt][e] = g[e];
        }
        int i1 = 0; float v1 = g[0];
        #pragma unroll
        for (int e = 1; e < NEXP; e++) if (g[e] > v1) { v1 = g[e]; i1 = e; }
        int i2 = -1; float v2 = -1e30f;
        #pragma unroll
        for (int e = 0; e < NEXP; e++) if (e != i1 && g[e] > v2) { v2 = g[e]; i2 = e; }
        float wsum = v1 + v2;
        float w1 = v1 / wsum, w2 = v2 / wsum;
        int p1 = atomicAdd(&g_cnt[i1], 1);
        g_tok[i1][p1] = token; g_wt[i1][p1] = w1;
        int p2 = atomicAdd(&g_cnt[i2], 1);
        g_tok[i2][p2] = token; g_wt[i2][p2] = w2;
    }
    __syncthreads();
    if (tid < NEXP) {
        float s = 0.f;
        #pragma unroll
        for (int t = 0; t < 32; t++) s += lg[t][tid];
        atomicAdd(&g_psum[tid], s);
    }
}

// ---------------- stage loader (bf16 tiles) ----------------
template<bool EXPERT>
__device__ __forceinline__ void load_stage(
    const uint16_t* __restrict__ Wb,
    int nb, int mb, const int* __restrict__ toks,
    uint32_t smem_base, int chunk, int buf, int tid)
{
    const uint32_t abase = smem_base + SMEM_HDR + buf * STAGE_BYTES;
    const uint32_t bbase = abase + A_STAGE_BYTES;
    const int k0 = chunk * BK;

    #pragma unroll
    for (int j = 0; j < 2; j++) {
        int idx = tid + j * 256;
        int row = idx >> 2, c = idx & 3;
        int tok = EXPERT ? toks[row] : (mb + row);
        cp16(abase + (uint32_t)(row * A_ROW_B + c * 16),
             g_xa + (size_t)tok * HIDDEN + k0 + c * 8);
    }
    #pragma unroll
    for (int j = 0; j < 2; j++) {
        int idx = tid + j * 256;
        int row = idx >> 4, c = idx & 15;
        cp16(bbase + (uint32_t)(row * B_ROW_B + c * 16),
             Wb + (size_t)(k0 + row) * HIDDEN + nb + c * 8);
    }
    CP_COMMIT();
}

// ---------------- GEMM tile body (bf16 mma.sync m16n8k16 + ldmatrix) ----------------
template<bool EXPERT>
__device__ __forceinline__ void gemm_tile(
    const uint16_t* __restrict__ Wb,
    const float* __restrict__ bias, float sc1,
    float* __restrict__ out, int mb, int nb, int cnt, int e)
{
    extern __shared__ char smem[];
    const uint32_t smem_base = smem_u32(smem);
    const int tid = threadIdx.x;
    const int wid = tid >> 5;
    const int lane = tid & 31;
    const int wm = wid & 1;
    const int wn = wid >> 1;

    int*   toks = (int*)smem;
    float* wts  = (float*)(smem + 512);

    if (EXPERT) {
        if (tid < 128) {
            int li = mb + tid;
            toks[tid] = (li < cnt) ? g_tok[e][li] : 0;
            wts[tid]  = (li < cnt) ? g_wt[e][li] : 0.f;
        }
        __syncthreads();
    }

    float acc[4][4][4];
    #pragma unroll
    for (int mt = 0; mt < 4; mt++)
        #pragma unroll
        for (int nt = 0; nt < 4; nt++)
            #pragma unroll
            for (int q = 0; q < 4; q++) acc[mt][nt][q] = 0.f;

    load_stage<EXPERT>(Wb, nb, mb, toks, smem_base, 0, 0, tid);
    load_stage<EXPERT>(Wb, nb, mb, toks, smem_base, 1, 1, tid);
    load_stage<EXPERT>(Wb, nb, mb, toks, smem_base, 2, 2, tid);

    const uint32_t a_warp = (uint32_t)((lane & 15) * A_ROW_B + (lane >> 4) * 16 + wm * 64 * A_ROW_B);
    const uint32_t b_warp = (uint32_t)((lane & 15) * B_ROW_B + (lane >> 4) * 16 + wn * 64);

    for (int i0 = 0; i0 < NCHUNKS; i0 += 4) {
        #pragma unroll
        for (int u = 0; u < 4; u++) {
            const int i = i0 + u;
            CP_WAIT(2);
            __syncthreads();

            if (i + 3 < NCHUNKS)
                load_stage<EXPERT>(Wb, nb, mb, toks, smem_base, i + 3, (u + 3) & 3, tid);
            else
                CP_COMMIT();

            const uint32_t ab = smem_base + SMEM_HDR + u * STAGE_BYTES + a_warp;
            const uint32_t bb = smem_base + SMEM_HDR + u * STAGE_BYTES + A_STAGE_BYTES + b_warp;

            #pragma unroll
            for (int ks = 0; ks < 2; ks++) {
                uint32_t af[4][4], bfr[2][4];
                #pragma unroll
                for (int mt = 0; mt < 4; mt++)
                    ldsm_x4(af[mt], ab + mt * (16 * A_ROW_B) + ks * 32);
                #pragma unroll
                for (int ng = 0; ng < 2; ng++)
                    ldsm_x4_t(bfr[ng], bb + ks * (16 * B_ROW_B) + ng * 32);
                #pragma unroll
                for (int mt = 0; mt < 4; mt++)
                    #pragma unroll
                    for (int ng = 0; ng < 2; ng++) {
                        mma_bf16(acc[mt][ng * 2 + 0], af[mt], bfr[ng][0], bfr[ng][1]);
                        mma_bf16(acc[mt][ng * 2 + 1], af[mt], bfr[ng][2], bfr[ng][3]);
                    }
            }
        }
    }

    const int lq = lane >> 2;
    const int lr = lane & 3;
    #pragma unroll
    for (int mt = 0; mt < 4; mt++) {
        #pragma unroll
        for (int h = 0; h < 2; h++) {
            int mrow = wm * 64 + mt * 16 + lq + h * 8;
            int token;
            float wscale;
            if (EXPERT) {
                if (mb + mrow >= cnt) continue;
                token = toks[mrow];
                wscale = sc1 * wts[mrow];
            } else {
                token = mb + mrow;
                wscale = sc1;
            }
            float* orow = out + (size_t)token * HIDDEN;
            #pragma unroll
            for (int nt = 0; nt < 4; nt++) {
                int col = nb + wn * 32 + nt * 8 + 2 * lr;
                float2 bv = *(const float2*)&bias[col];
                float s0 = wscale * sigf(acc[mt][nt][2 * h]     + bv.x);
                float s1 = wscale * sigf(acc[mt][nt][2 * h + 1] + bv.y);
                red_add_v2(orow + col, s0, s1);
            }
        }
    }
}

// ---------------- K2: fused shared + expert GEMM ----------------
__global__ __launch_bounds__(256, 2)
void fused_gemm(const float* __restrict__ SBias, const float* __restrict__ p_ss,
                const float* __restrict__ EBias, const float* __restrict__ p_rs,
                float* __restrict__ out)
{
    const int nb = blockIdx.y * TILE_N;
    const int mb = blockIdx.x * TILE_M;
    if (blockIdx.z == NEXP) {
        gemm_tile<false>(g_wb + (size_t)NEXP * HIDDEN * HIDDEN, SBias, p_ss[0],
                         out, mb, nb, BTOK, 0);
    } else {
        const int e = blockIdx.z;
        const int cnt = g_cnt[e];
        if (mb >= cnt) return;
        gemm_tile<true>(g_wb + (size_t)e * HIDDEN * HIDDEN,
                        EBias + (size_t)e * HIDDEN, p_rs[0], out, mb, nb, cnt, e);
    }
}

// ---------------- K4: gate loss ----------------
__global__ void loss_kernel(float* __restrict__ out, int out_size) {
    if (threadIdx.x == 0) {
        float acc = 0.f;
        #pragma unroll
        for (int e = 0; e < NEXP; e++) {
            float p = g_psum[e] * (1.f / (float)BTOK);
            float d = 0.125f - p;
            acc += d * d;
        }
        float loss = acc * (0.01f / 8.f);
        for (long long i = (long long)BTOK * HIDDEN; i < out_size; i++)
            out[i] = loss;
    }
}

// ---------------- launcher ----------------
extern "C" void kernel_launch(void* const* d_in, const int* in_sizes, int n_in,
                              void* d_out, int out_size) {
    const float* x      = (const float*)d_in[0];
    const float* noise  = (const float*)d_in[1];
    const float* gw1    = (const float*)d_in[2];
    const float* gb1    = (const float*)d_in[3];
    const float* gw2    = (const float*)d_in[4];
    const float* gb2    = (const float*)d_in[5];
    const float* sw     = (const float*)d_in[6];
    const float* sb     = (const float*)d_in[7];
    const float* sscale = (const float*)d_in[8];
    const float* ew     = (const float*)d_in[9];
    const float* eb     = (const float*)d_in[10];
    const float* rscale = (const float*)d_in[11];
    float* out = (float*)d_out;

    static bool attr_done = false;
    if (!attr_done) {
        cudaFuncSetAttribute(fused_gemm, cudaFuncAttributeMaxDynamicSharedMemorySize, SMEM_TOTAL);
        attr_done = true;
    }

    init_kernel<<<1, 32>>>();
    convert_x<<<(BTOK * HIDDEN / 4) / 256, 256>>>(x, rscale, out);
    convert_w<<<((NEXP + 1) * (HIDDEN * HIDDEN / 4)) / 256, 256>>>(ew, sw);
    gating_kernel<<<128, 256>>>(x, noise, gw1, gb1, gw2, gb2);
    fused_gemm<<<dim3(BTOK / TILE_M, HIDDEN / TILE_N, NEXP + 1), 256, SMEM_TOTAL>>>(
        sb, sscale, eb, rscale, out);
    loss_kernel<<<1, 32>>>(out, out_size);
}

// round 9
// speedup vs baseline: 6.5753x; 1.0194x over previous
#include <cuda_runtime.h>
#include <cuda_bf16.h>
#include <cstdint>
#include <math.h>

#define HIDDEN 2048
#define NEXP 8
#define GDIM 64
#define BTOK 4096

#define TILE_M 128
#define TILE_N 128
#define BK 32
#define NCHUNKS (HIDDEN / BK)       // 64
#define NSTAGE 4

// bf16 smem tiles
#define A_ROW_B 80
#define B_ROW_B 272
#define A_STAGE_BYTES (128 * A_ROW_B)  // 10240
#define B_STAGE_BYTES (BK * B_ROW_B)   // 8704
#define STAGE_BYTES (A_STAGE_BYTES + B_STAGE_BYTES) // 18944
#define SMEM_HDR 1024
#define SMEM_TOTAL (SMEM_HDR + NSTAGE * STAGE_BYTES) // 76800 -> 2 CTAs/SM

// mega-kernel block ranges
#define GBLK 256                                   // gating: 16 tokens each
#define CXBLK (BTOK * HIDDEN / 4 / 256)            // 8192
#define CWBLK ((NEXP + 1) * HIDDEN * HIDDEN / 4 / 256) // 36864
#define MEGA_BLOCKS (GBLK + CXBLK + CWBLK)

// ---------------- device scratch ----------------
__device__ int   g_cnt[NEXP];
__device__ int   g_tok[NEXP][BTOK];
__device__ float g_wt[NEXP][BTOK];
__device__ float g_psum[NEXP];
__device__ uint16_t g_xa[(size_t)BTOK * HIDDEN];
__device__ uint16_t g_wb[(size_t)(NEXP + 1) * HIDDEN * HIDDEN];

// ---------------- helpers ----------------
__device__ __forceinline__ uint32_t smem_u32(const void* p) {
    uint32_t a;
    asm("{ .reg .u64 t; cvta.to.shared.u64 t, %1; cvt.u32.u64 %0, t; }" : "=r"(a) : "l"(p));
    return a;
}
__device__ __forceinline__ void cp16(uint32_t dst, const void* src) {
    asm volatile("cp.async.cg.shared.global [%0], [%1], 16;" :: "r"(dst), "l"(src));
}
#define CP_COMMIT() asm volatile("cp.async.commit_group;" ::: "memory")
#define CP_WAIT(n)  asm volatile("cp.async.wait_group %0;" :: "n"(n) : "memory")

__device__ __forceinline__ void ldsm_x4(uint32_t* r, uint32_t addr) {
    asm volatile("ldmatrix.sync.aligned.m8n8.x4.shared.b16 {%0,%1,%2,%3}, [%4];"
        : "=r"(r[0]), "=r"(r[1]), "=r"(r[2]), "=r"(r[3]) : "r"(addr));
}
__device__ __forceinline__ void ldsm_x4_t(uint32_t* r, uint32_t addr) {
    asm volatile("ldmatrix.sync.aligned.m8n8.x4.trans.shared.b16 {%0,%1,%2,%3}, [%4];"
        : "=r"(r[0]), "=r"(r[1]), "=r"(r[2]), "=r"(r[3]) : "r"(addr));
}
__device__ __forceinline__ void mma_bf16(float* d, const uint32_t* a, uint32_t b0, uint32_t b1) {
    asm volatile(
        "mma.sync.aligned.m16n8k16.row.col.f32.bf16.bf16.f32 "
        "{%0,%1,%2,%3}, {%4,%5,%6,%7}, {%8,%9}, {%0,%1,%2,%3};"
        : "+f"(d[0]), "+f"(d[1]), "+f"(d[2]), "+f"(d[3])
        : "r"(a[0]), "r"(a[1]), "r"(a[2]), "r"(a[3]), "r"(b0), "r"(b1));
}
__device__ __forceinline__ uint32_t pack_bf16(float lo, float hi) {
    uint32_t r;
    asm("cvt.rn.bf16x2.f32 %0, %1, %2;" : "=r"(r) : "f"(hi), "f"(lo));
    return r;
}
__device__ __forceinline__ void red_add_v2(float* p, float a, float b) {
    asm volatile("red.global.add.v2.f32 [%0], {%1, %2};" :: "l"(p), "f"(a), "f"(b) : "memory");
}
__device__ __forceinline__ float sigf(float z) { return 1.f / (1.f + __expf(-z)); }

// ---------------- K0: zero counters ----------------
__global__ void init_kernel() {
    int t = threadIdx.x;
    if (t < NEXP) { g_cnt[t] = 0; g_psum[t] = 0.f; }
}

// ---------------- K1: mega kernel: gating + convert_x + convert_w ----------------
#define GK 32
__global__ __launch_bounds__(256) void mega_kernel(
    const float* __restrict__ X, const float* __restrict__ noise,
    const float* __restrict__ gw1, const float* __restrict__ gb1,
    const float* __restrict__ gw2, const float* __restrict__ gb2,
    const float* __restrict__ EW, const float* __restrict__ SW,
    const float* __restrict__ p_rs, float* __restrict__ out)
{
    const int bid = blockIdx.x;
    const int tid = threadIdx.x;

    if (bid >= GBLK) {
        // ---- convert roles (no smem use) ----
        if (bid < GBLK + CXBLK) {
            size_t t = (size_t)(bid - GBLK) * 256 + tid;
            float4 v = ((const float4*)X)[t];
            uint2 p;
            p.x = pack_bf16(v.x, v.y);
            p.y = pack_bf16(v.z, v.w);
            ((uint2*)g_xa)[t] = p;
            const float s = 1.f + p_rs[0];
            ((float4*)out)[t] = make_float4(s * v.x, s * v.y, s * v.z, s * v.w);
        } else {
            size_t t = (size_t)(bid - GBLK - CXBLK) * 256 + tid;
            size_t elem = t * 4;
            const size_t EXP_ELEMS = (size_t)NEXP * HIDDEN * HIDDEN;
            float4 v = (elem < EXP_ELEMS) ? ((const float4*)EW)[t]
                                          : *(const float4*)(SW + (elem - EXP_ELEMS));
            uint2 p;
            p.x = pack_bf16(v.x, v.y);
            p.y = pack_bf16(v.z, v.w);
            ((uint2*)g_wb)[t] = p;
        }
        return;
    }

    // ---- gating role: 16 tokens per block ----
    __shared__ float xs[2][16][36];
    __shared__ float ws[2][GK][68];
    __shared__ float hs[16][65];
    __shared__ float lg[16][NEXP];
    __shared__ float ws2[GDIM * NEXP];
    __shared__ float bs2[NEXP];

    const int tok0 = bid * 16;
    const int j = tid & 63;
    const int r = tid >> 6;

    const uint32_t xs_b = smem_u32(&xs[0][0][0]);
    const uint32_t ws_b = smem_u32(&ws[0][0][0]);

    ws2[tid]       = gw2[tid];
    ws2[tid + 256] = gw2[tid + 256];
    if (tid < NEXP) bs2[tid] = gb2[tid];

    auto stage = [&](int c, int b) {
        int k0 = c * GK;
        if (tid < 128) {   // X: 16 rows x 32 floats -> 128 cp16
            int row = tid >> 3, q = tid & 7;
            cp16(xs_b + (uint32_t)(b * 16 * 36 * 4 + row * 36 * 4 + q * 16),
                 &X[(size_t)(tok0 + row) * HIDDEN + k0 + q * 4]);
        }
        #pragma unroll
        for (int jj = 0; jj < 2; jj++) {   // W: 32 rows x 64 floats -> 512 cp16
            int idx = tid + jj * 256;
            int row = idx >> 4, q = idx & 15;
            cp16(ws_b + (uint32_t)(b * GK * 68 * 4 + row * 68 * 4 + q * 16),
                 &gw1[(size_t)(k0 + row) * GDIM + q * 4]);
        }
        CP_COMMIT();
    };

    float acc[4];
    const float b1 = gb1[j];
    #pragma unroll
    for (int u = 0; u < 4; u++) acc[u] = b1;

    stage(0, 0);
    for (int c = 0; c < HIDDEN / GK; c++) {
        const int buf = c & 1;
        if (c + 1 < HIDDEN / GK) stage(c + 1, (c + 1) & 1);
        else CP_COMMIT();
        CP_WAIT(1);
        __syncthreads();
        #pragma unroll 8
        for (int kk = 0; kk < GK; kk++) {
            float w = ws[buf][kk][j];
            #pragma unroll
            for (int u = 0; u < 4; u++) acc[u] = fmaf(xs[buf][r + 4 * u][kk], w, acc[u]);
        }
        __syncthreads();
    }
    #pragma unroll
    for (int u = 0; u < 4; u++) hs[r + 4 * u][j] = fmaxf(acc[u], 0.f);
    __syncthreads();

    if (tid < 128) {
        int lt = tid >> 3, e = tid & 7;
        float a = bs2[e];
        #pragma unroll 8
        for (int k = 0; k < GDIM; k++) a = fmaf(hs[lt][k], ws2[k * NEXP + e], a);
        lg[lt][e] = a;
    }
    __syncthreads();

    if (tid < 16) {
        int lt = tid;
        int token = tok0 + lt;
        float g[NEXP];
        float m = -1e30f;
        #pragma unroll
        for (int e = 0; e < NEXP; e++) { g[e] = lg[lt][e]; m = fmaxf(m, g[e]); }
        float s = 0.f;
        #pragma unroll
        for (int e = 0; e < NEXP; e++) { g[e] = expf(g[e] - m); s += g[e]; }
        float inv = 1.f / s;
        #pragma unroll
        for (int e = 0; e < NEXP; e++) {
            g[e] = g[e] * inv + noise[token * NEXP + e] * 0.01f;
            lg[lt][e] = g[e];
        }
        int i1 = 0; float v1 = g[0];
        #pragma unroll
        for (int e = 1; e < NEXP; e++) if (g[e] > v1) { v1 = g[e]; i1 = e; }
        int i2 = -1; float v2 = -1e30f;
        #pragma unroll
        for (int e = 0; e < NEXP; e++) if (e != i1 && g[e] > v2) { v2 = g[e]; i2 = e; }
        float wsum = v1 + v2;
        float w1 = v1 / wsum, w2 = v2 / wsum;
        int p1 = atomicAdd(&g_cnt[i1], 1);
        g_tok[i1][p1] = token; g_wt[i1][p1] = w1;
        int p2 = atomicAdd(&g_cnt[i2], 1);
        g_tok[i2][p2] = token; g_wt[i2][p2] = w2;
    }
    __syncthreads();
    if (tid < NEXP) {
        float s = 0.f;
        #pragma unroll
        for (int t = 0; t < 16; t++) s += lg[t][tid];
        atomicAdd(&g_psum[tid], s);
    }
}

// ---------------- stage loader (bf16 tiles) ----------------
template<bool EXPERT>
__device__ __forceinline__ void load_stage(
    const uint16_t* __restrict__ Wb,
    int nb, int mb, const int* __restrict__ toks,
    uint32_t smem_base, int chunk, int buf, int tid)
{
    const uint32_t abase = smem_base + SMEM_HDR + buf * STAGE_BYTES;
    const uint32_t bbase = abase + A_STAGE_BYTES;
    const int k0 = chunk * BK;

    #pragma unroll
    for (int j = 0; j < 2; j++) {
        int idx = tid + j * 256;
        int row = idx >> 2, c = idx & 3;
        int tok = EXPERT ? toks[row] : (mb + row);
        cp16(abase + (uint32_t)(row * A_ROW_B + c * 16),
             g_xa + (size_t)tok * HIDDEN + k0 + c * 8);
    }
    #pragma unroll
    for (int j = 0; j < 2; j++) {
        int idx = tid + j * 256;
        int row = idx >> 4, c = idx & 15;
        cp16(bbase + (uint32_t)(row * B_ROW_B + c * 16),
             Wb + (size_t)(k0 + row) * HIDDEN + nb + c * 8);
    }
    CP_COMMIT();
}

// ---------------- GEMM tile body ----------------
template<bool EXPERT>
__device__ __forceinline__ void gemm_tile(
    const uint16_t* __restrict__ Wb,
    const float* __restrict__ bias, float sc1,
    float* __restrict__ out, int mb, int nb, int cnt, int e)
{
    extern __shared__ char smem[];
    const uint32_t smem_base = smem_u32(smem);
    const int tid = threadIdx.x;
    const int wid = tid >> 5;
    const int lane = tid & 31;
    const int wm = wid & 1;
    const int wn = wid >> 1;

    int*   toks = (int*)smem;
    float* wts  = (float*)(smem + 512);

    if (EXPERT) {
        if (tid < 128) {
            int li = mb + tid;
            toks[tid] = (li < cnt) ? g_tok[e][li] : 0;
            wts[tid]  = (li < cnt) ? g_wt[e][li] : 0.f;
        }
        __syncthreads();
    }

    float acc[4][4][4];
    #pragma unroll
    for (int mt = 0; mt < 4; mt++)
        #pragma unroll
        for (int nt = 0; nt < 4; nt++)
            #pragma unroll
            for (int q = 0; q < 4; q++) acc[mt][nt][q] = 0.f;

    load_stage<EXPERT>(Wb, nb, mb, toks, smem_base, 0, 0, tid);
    load_stage<EXPERT>(Wb, nb, mb, toks, smem_base, 1, 1, tid);
    load_stage<EXPERT>(Wb, nb, mb, toks, smem_base, 2, 2, tid);

    const uint32_t a_warp = (uint32_t)((lane & 15) * A_ROW_B + (lane >> 4) * 16 + wm * 64 * A_ROW_B);
    const uint32_t b_warp = (uint32_t)((lane & 15) * B_ROW_B + (lane >> 4) * 16 + wn * 64);

    for (int i0 = 0; i0 < NCHUNKS; i0 += 4) {
        #pragma unroll
        for (int u = 0; u < 4; u++) {
            const int i = i0 + u;
            CP_WAIT(2);
            __syncthreads();

            if (i + 3 < NCHUNKS)
                load_stage<EXPERT>(Wb, nb, mb, toks, smem_base, i + 3, (u + 3) & 3, tid);
            else
                CP_COMMIT();

            const uint32_t ab = smem_base + SMEM_HDR + u * STAGE_BYTES + a_warp;
            const uint32_t bb = smem_base + SMEM_HDR + u * STAGE_BYTES + A_STAGE_BYTES + b_warp;

            #pragma unroll
            for (int ks = 0; ks < 2; ks++) {
                uint32_t af[4][4], bfr[2][4];
                #pragma unroll
                for (int mt = 0; mt < 4; mt++)
                    ldsm_x4(af[mt], ab + mt * (16 * A_ROW_B) + ks * 32);
                #pragma unroll
                for (int ng = 0; ng < 2; ng++)
                    ldsm_x4_t(bfr[ng], bb + ks * (16 * B_ROW_B) + ng * 32);
                #pragma unroll
                for (int mt = 0; mt < 4; mt++)
                    #pragma unroll
                    for (int ng = 0; ng < 2; ng++) {
                        mma_bf16(acc[mt][ng * 2 + 0], af[mt], bfr[ng][0], bfr[ng][1]);
                        mma_bf16(acc[mt][ng * 2 + 1], af[mt], bfr[ng][2], bfr[ng][3]);
                    }
            }
        }
    }

    const int lq = lane >> 2;
    const int lr = lane & 3;
    #pragma unroll
    for (int mt = 0; mt < 4; mt++) {
        #pragma unroll
        for (int h = 0; h < 2; h++) {
            int mrow = wm * 64 + mt * 16 + lq + h * 8;
            int token;
            float wscale;
            if (EXPERT) {
                if (mb + mrow >= cnt) continue;
                token = toks[mrow];
                wscale = sc1 * wts[mrow];
            } else {
                token = mb + mrow;
                wscale = sc1;
            }
            float* orow = out + (size_t)token * HIDDEN;
            #pragma unroll
            for (int nt = 0; nt < 4; nt++) {
                int col = nb + wn * 32 + nt * 8 + 2 * lr;
                float2 bv = *(const float2*)&bias[col];
                float s0 = wscale * sigf(acc[mt][nt][2 * h]     + bv.x);
                float s1 = wscale * sigf(acc[mt][nt][2 * h + 1] + bv.y);
                red_add_v2(orow + col, s0, s1);
            }
        }
    }
}

// ---------------- K2: fused shared + expert GEMM ----------------
__global__ __launch_bounds__(256, 2)
void fused_gemm(const float* __restrict__ SBias, const float* __restrict__ p_ss,
                const float* __restrict__ EBias, const float* __restrict__ p_rs,
                float* __restrict__ out)
{
    const int nb = blockIdx.y * TILE_N;
    const int mb = blockIdx.x * TILE_M;
    if (blockIdx.z == NEXP) {
        gemm_tile<false>(g_wb + (size_t)NEXP * HIDDEN * HIDDEN, SBias, p_ss[0],
                         out, mb, nb, BTOK, 0);
    } else {
        const int e = blockIdx.z;
        const int cnt = g_cnt[e];
        if (mb >= cnt) return;
        gemm_tile<true>(g_wb + (size_t)e * HIDDEN * HIDDEN,
                        EBias + (size_t)e * HIDDEN, p_rs[0], out, mb, nb, cnt, e);
    }
}

// ---------------- K3: gate loss ----------------
__global__ void loss_kernel(float* __restrict__ out, int out_size) {
    if (threadIdx.x == 0) {
        float acc = 0.f;
        #pragma unroll
        for (int e = 0; e < NEXP; e++) {
            float p = g_psum[e] * (1.f / (float)BTOK);
            float d = 0.125f - p;
            acc += d * d;
        }
        float loss = acc * (0.01f / 8.f);
        for (long long i = (long long)BTOK * HIDDEN; i < out_size; i++)
            out[i] = loss;
    }
}

// ---------------- launcher ----------------
extern "C" void kernel_launch(void* const* d_in, const int* in_sizes, int n_in,
                              void* d_out, int out_size) {
    const float* x      = (const float*)d_in[0];
    const float* noise  = (const float*)d_in[1];
    const float* gw1    = (const float*)d_in[2];
    const float* gb1    = (const float*)d_in[3];
    const float* gw2    = (const float*)d_in[4];
    const float* gb2    = (const float*)d_in[5];
    const float* sw     = (const float*)d_in[6];
    const float* sb     = (const float*)d_in[7];
    const float* sscale = (const float*)d_in[8];
    const float* ew     = (const float*)d_in[9];
    const float* eb     = (const float*)d_in[10];
    const float* rscale = (const float*)d_in[11];
    float* out = (float*)d_out;

    static bool attr_done = false;
    if (!attr_done) {
        cudaFuncSetAttribute(fused_gemm, cudaFuncAttributeMaxDynamicSharedMemorySize, SMEM_TOTAL);
        attr_done = true;
    }

    init_kernel<<<1, 32>>>();
    mega_kernel<<<MEGA_BLOCKS, 256>>>(x, noise, gw1, gb1, gw2, gb2, ew, sw, rscale, out);
    fused_gemm<<<dim3(BTOK / TILE_M, HIDDEN / TILE_N, NEXP + 1), 256, SMEM_TOTAL>>>(
        sb, sscale, eb, rscale, out);
    loss_kernel<<<1, 32>>>(out, out_size);
}

// round 10
// speedup vs baseline: 6.6535x; 1.0119x over previous
#include <cuda_runtime.h>
#include <cuda_bf16.h>
#include <cstdint>
#include <math.h>

#define HIDDEN 2048
#define NEXP 8
#define GDIM 64
#define BTOK 4096

#define TILE_M 128
#define TILE_N 128
#define BK 64
#define NCHUNKS (HIDDEN / BK)       // 32
#define NSTAGE 3

// bf16 smem tiles
#define A_ROW_B 144                  // 64 bf16 (128B) + 16B pad
#define B_ROW_B 272                  // 128 bf16 (256B) + 16B pad
#define A_STAGE_BYTES (128 * A_ROW_B)  // 18432
#define B_STAGE_BYTES (BK * B_ROW_B)   // 17408
#define STAGE_BYTES (A_STAGE_BYTES + B_STAGE_BYTES) // 35840
#define SMEM_HDR 1024
#define SMEM_TOTAL (SMEM_HDR + NSTAGE * STAGE_BYTES) // 108544 -> 2 CTAs/SM

// mega-kernel block ranges
#define GBLK 256
#define CXBLK (BTOK * HIDDEN / 4 / 256)
#define CWBLK ((NEXP + 1) * HIDDEN * HIDDEN / 4 / 256)
#define MEGA_BLOCKS (GBLK + CXBLK + CWBLK)

// ---------------- device scratch ----------------
__device__ int   g_cnt[NEXP];
__device__ int   g_tok[NEXP][BTOK];
__device__ float g_wt[NEXP][BTOK];
__device__ float g_psum[NEXP];
__device__ uint16_t g_xa[(size_t)BTOK * HIDDEN];
__device__ uint16_t g_wb[(size_t)(NEXP + 1) * HIDDEN * HIDDEN];

// ---------------- helpers ----------------
__device__ __forceinline__ uint32_t smem_u32(const void* p) {
    uint32_t a;
    asm("{ .reg .u64 t; cvta.to.shared.u64 t, %1; cvt.u32.u64 %0, t; }" : "=r"(a) : "l"(p));
    return a;
}
__device__ __forceinline__ void cp16(uint32_t dst, const void* src) {
    asm volatile("cp.async.cg.shared.global [%0], [%1], 16;" :: "r"(dst), "l"(src));
}
#define CP_COMMIT() asm volatile("cp.async.commit_group;" ::: "memory")
#define CP_WAIT(n)  asm volatile("cp.async.wait_group %0;" :: "n"(n) : "memory")

__device__ __forceinline__ void ldsm_x4(uint32_t* r, uint32_t addr) {
    asm volatile("ldmatrix.sync.aligned.m8n8.x4.shared.b16 {%0,%1,%2,%3}, [%4];"
        : "=r"(r[0]), "=r"(r[1]), "=r"(r[2]), "=r"(r[3]) : "r"(addr));
}
__device__ __forceinline__ void ldsm_x4_t(uint32_t* r, uint32_t addr) {
    asm volatile("ldmatrix.sync.aligned.m8n8.x4.trans.shared.b16 {%0,%1,%2,%3}, [%4];"
        : "=r"(r[0]), "=r"(r[1]), "=r"(r[2]), "=r"(r[3]) : "r"(addr));
}
__device__ __forceinline__ void mma_bf16(float* d, const uint32_t* a, uint32_t b0, uint32_t b1) {
    asm volatile(
        "mma.sync.aligned.m16n8k16.row.col.f32.bf16.bf16.f32 "
        "{%0,%1,%2,%3}, {%4,%5,%6,%7}, {%8,%9}, {%0,%1,%2,%3};"
        : "+f"(d[0]), "+f"(d[1]), "+f"(d[2]), "+f"(d[3])
        : "r"(a[0]), "r"(a[1]), "r"(a[2]), "r"(a[3]), "r"(b0), "r"(b1));
}
__device__ __forceinline__ uint32_t pack_bf16(float lo, float hi) {
    uint32_t r;
    asm("cvt.rn.bf16x2.f32 %0, %1, %2;" : "=r"(r) : "f"(hi), "f"(lo));
    return r;
}
__device__ __forceinline__ void red_add_v2(float* p, float a, float b) {
    asm volatile("red.global.add.v2.f32 [%0], {%1, %2};" :: "l"(p), "f"(a), "f"(b) : "memory");
}
__device__ __forceinline__ float sigf(float z) { return 1.f / (1.f + __expf(-z)); }

// ---------------- K0: zero counters ----------------
__global__ void init_kernel() {
    int t = threadIdx.x;
    if (t < NEXP) { g_cnt[t] = 0; g_psum[t] = 0.f; }
}

// ---------------- K1: mega kernel: gating + convert_x + convert_w ----------------
#define GK 32
__global__ __launch_bounds__(256) void mega_kernel(
    const float* __restrict__ X, const float* __restrict__ noise,
    const float* __restrict__ gw1, const float* __restrict__ gb1,
    const float* __restrict__ gw2, const float* __restrict__ gb2,
    const float* __restrict__ EW, const float* __restrict__ SW,
    const float* __restrict__ p_rs, float* __restrict__ out)
{
    const int bid = blockIdx.x;
    const int tid = threadIdx.x;

    if (bid >= GBLK) {
        if (bid < GBLK + CXBLK) {
            size_t t = (size_t)(bid - GBLK) * 256 + tid;
            float4 v = ((const float4*)X)[t];
            uint2 p;
            p.x = pack_bf16(v.x, v.y);
            p.y = pack_bf16(v.z, v.w);
            ((uint2*)g_xa)[t] = p;
            const float s = 1.f + p_rs[0];
            ((float4*)out)[t] = make_float4(s * v.x, s * v.y, s * v.z, s * v.w);
        } else {
            size_t t = (size_t)(bid - GBLK - CXBLK) * 256 + tid;
            size_t elem = t * 4;
            const size_t EXP_ELEMS = (size_t)NEXP * HIDDEN * HIDDEN;
            float4 v = (elem < EXP_ELEMS) ? ((const float4*)EW)[t]
                                          : *(const float4*)(SW + (elem - EXP_ELEMS));
            uint2 p;
            p.x = pack_bf16(v.x, v.y);
            p.y = pack_bf16(v.z, v.w);
            ((uint2*)g_wb)[t] = p;
        }
        return;
    }

    // ---- gating role: 16 tokens per block, 4-deep cp.async pipeline ----
    __shared__ float xs[4][16][36];
    __shared__ float ws[4][GK][68];
    __shared__ float hs[16][65];
    __shared__ float lg[16][NEXP];
    __shared__ float ws2[GDIM * NEXP];
    __shared__ float bs2[NEXP];

    const int tok0 = bid * 16;
    const int j = tid & 63;
    const int r = tid >> 6;

    const uint32_t xs_b = smem_u32(&xs[0][0][0]);
    const uint32_t ws_b = smem_u32(&ws[0][0][0]);

    ws2[tid]       = gw2[tid];
    ws2[tid + 256] = gw2[tid + 256];
    if (tid < NEXP) bs2[tid] = gb2[tid];

    auto stage = [&](int c, int b) {
        int k0 = c * GK;
        if (tid < 128) {
            int row = tid >> 3, q = tid & 7;
            cp16(xs_b + (uint32_t)(b * 16 * 36 * 4 + row * 36 * 4 + q * 16),
                 &X[(size_t)(tok0 + row) * HIDDEN + k0 + q * 4]);
        }
        #pragma unroll
        for (int jj = 0; jj < 2; jj++) {
            int idx = tid + jj * 256;
            int row = idx >> 4, q = idx & 15;
            cp16(ws_b + (uint32_t)(b * GK * 68 * 4 + row * 68 * 4 + q * 16),
                 &gw1[(size_t)(k0 + row) * GDIM + q * 4]);
        }
        CP_COMMIT();
    };

    float acc[4];
    const float b1 = gb1[j];
    #pragma unroll
    for (int u = 0; u < 4; u++) acc[u] = b1;

    stage(0, 0); stage(1, 1); stage(2, 2);
    for (int c = 0; c < HIDDEN / GK; c++) {
        const int buf = c & 3;
        if (c + 3 < HIDDEN / GK) stage(c + 3, (c + 3) & 3);
        else CP_COMMIT();
        CP_WAIT(3);
        __syncthreads();
        #pragma unroll 8
        for (int kk = 0; kk < GK; kk++) {
            float w = ws[buf][kk][j];
            #pragma unroll
            for (int u = 0; u < 4; u++) acc[u] = fmaf(xs[buf][r + 4 * u][kk], w, acc[u]);
        }
        __syncthreads();
    }
    #pragma unroll
    for (int u = 0; u < 4; u++) hs[r + 4 * u][j] = fmaxf(acc[u], 0.f);
    __syncthreads();

    if (tid < 128) {
        int lt = tid >> 3, e = tid & 7;
        float a = bs2[e];
        #pragma unroll 8
        for (int k = 0; k < GDIM; k++) a = fmaf(hs[lt][k], ws2[k * NEXP + e], a);
        lg[lt][e] = a;
    }
    __syncthreads();

    if (tid < 16) {
        int lt = tid;
        int token = tok0 + lt;
        float g[NEXP];
        float m = -1e30f;
        #pragma unroll
        for (int e = 0; e < NEXP; e++) { g[e] = lg[lt][e]; m = fmaxf(m, g[e]); }
        float s = 0.f;
        #pragma unroll
        for (int e = 0; e < NEXP; e++) { g[e] = expf(g[e] - m); s += g[e]; }
        float inv = 1.f / s;
        #pragma unroll
        for (int e = 0; e < NEXP; e++) {
            g[e] = g[e] * inv + noise[token * NEXP + e] * 0.01f;
            lg[lt][e] = g[e];
        }
        int i1 = 0; float v1 = g[0];
        #pragma unroll
        for (int e = 1; e < NEXP; e++) if (g[e] > v1) { v1 = g[e]; i1 = e; }
        int i2 = -1; float v2 = -1e30f;
        #pragma unroll
        for (int e = 0; e < NEXP; e++) if (e != i1 && g[e] > v2) { v2 = g[e]; i2 = e; }
        float wsum = v1 + v2;
        float w1 = v1 / wsum, w2 = v2 / wsum;
        int p1 = atomicAdd(&g_cnt[i1], 1);
        g_tok[i1][p1] = token; g_wt[i1][p1] = w1;
        int p2 = atomicAdd(&g_cnt[i2], 1);
        g_tok[i2][p2] = token; g_wt[i2][p2] = w2;
    }
    __syncthreads();
    if (tid < NEXP) {
        float s = 0.f;
        #pragma unroll
        for (int t = 0; t < 16; t++) s += lg[t][tid];
        atomicAdd(&g_psum[tid], s);
    }
}

// ---------------- stage loader (bf16 tiles, BK=64) ----------------
template<bool EXPERT>
__device__ __forceinline__ void load_stage(
    const uint16_t* __restrict__ Wb,
    int nb, int mb, const int* __restrict__ toks,
    uint32_t smem_base, int chunk, int buf, int tid)
{
    const uint32_t abase = smem_base + SMEM_HDR + buf * STAGE_BYTES;
    const uint32_t bbase = abase + A_STAGE_BYTES;
    const int k0 = chunk * BK;

    // A: 128 rows x 64 bf16 (8x16B per row) -> 1024 cp16
    #pragma unroll
    for (int j = 0; j < 4; j++) {
        int idx = tid + j * 256;
        int row = idx >> 3, c = idx & 7;
        int tok = EXPERT ? toks[row] : (mb + row);
        cp16(abase + (uint32_t)(row * A_ROW_B + c * 16),
             g_xa + (size_t)tok * HIDDEN + k0 + c * 8);
    }
    // B: 64 k-rows x 128 n bf16 (16x16B per row) -> 1024 cp16
    #pragma unroll
    for (int j = 0; j < 4; j++) {
        int idx = tid + j * 256;
        int row = idx >> 4, c = idx & 15;
        cp16(bbase + (uint32_t)(row * B_ROW_B + c * 16),
             Wb + (size_t)(k0 + row) * HIDDEN + nb + c * 8);
    }
    CP_COMMIT();
}

// ---------------- GEMM tile body ----------------
template<bool EXPERT>
__device__ __forceinline__ void gemm_tile(
    const uint16_t* __restrict__ Wb,
    const float* __restrict__ bias, float sc1,
    float* __restrict__ out, int mb, int nb, int cnt, int e)
{
    extern __shared__ char smem[];
    const uint32_t smem_base = smem_u32(smem);
    const int tid = threadIdx.x;
    const int wid = tid >> 5;
    const int lane = tid & 31;
    const int wm = wid & 1;
    const int wn = wid >> 1;

    int*   toks = (int*)smem;
    float* wts  = (float*)(smem + 512);

    if (EXPERT) {
        if (tid < 128) {
            int li = mb + tid;
            toks[tid] = (li < cnt) ? g_tok[e][li] : 0;
            wts[tid]  = (li < cnt) ? g_wt[e][li] : 0.f;
        }
        __syncthreads();
    }

    float acc[4][4][4];
    #pragma unroll
    for (int mt = 0; mt < 4; mt++)
        #pragma unroll
        for (int nt = 0; nt < 4; nt++)
            #pragma unroll
            for (int q = 0; q < 4; q++) acc[mt][nt][q] = 0.f;

    load_stage<EXPERT>(Wb, nb, mb, toks, smem_base, 0, 0, tid);
    load_stage<EXPERT>(Wb, nb, mb, toks, smem_base, 1, 1, tid);

    const uint32_t a_warp = (uint32_t)((lane & 15) * A_ROW_B + (lane >> 4) * 16 + wm * 64 * A_ROW_B);
    const uint32_t b_warp = (uint32_t)((lane & 15) * B_ROW_B + (lane >> 4) * 16 + wn * 64);

    for (int i = 0; i < NCHUNKS; i++) {
        const int buf = i % NSTAGE;
        CP_WAIT(1);
        __syncthreads();

        if (i + 2 < NCHUNKS)
            load_stage<EXPERT>(Wb, nb, mb, toks, smem_base, i + 2, (i + 2) % NSTAGE, tid);
        else
            CP_COMMIT();

        const uint32_t ab = smem_base + SMEM_HDR + buf * STAGE_BYTES + a_warp;
        const uint32_t bb = smem_base + SMEM_HDR + buf * STAGE_BYTES + A_STAGE_BYTES + b_warp;

        #pragma unroll
        for (int ks = 0; ks < 4; ks++) {
            uint32_t af[4][4], bfr[2][4];
            #pragma unroll
            for (int mt = 0; mt < 4; mt++)
                ldsm_x4(af[mt], ab + mt * (16 * A_ROW_B) + ks * 32);
            #pragma unroll
            for (int ng = 0; ng < 2; ng++)
                ldsm_x4_t(bfr[ng], bb + ks * (16 * B_ROW_B) + ng * 32);
            #pragma unroll
            for (int mt = 0; mt < 4; mt++)
                #pragma unroll
                for (int ng = 0; ng < 2; ng++) {
                    mma_bf16(acc[mt][ng * 2 + 0], af[mt], bfr[ng][0], bfr[ng][1]);
                    mma_bf16(acc[mt][ng * 2 + 1], af[mt], bfr[ng][2], bfr[ng][3]);
                }
        }
    }

    const int lq = lane >> 2;
    const int lr = lane & 3;
    #pragma unroll
    for (int mt = 0; mt < 4; mt++) {
        #pragma unroll
        for (int h = 0; h < 2; h++) {
            int mrow = wm * 64 + mt * 16 + lq + h * 8;
            int token;
            float wscale;
            if (EXPERT) {
                if (mb + mrow >= cnt) continue;
                token = toks[mrow];
                wscale = sc1 * wts[mrow];
            } else {
                token = mb + mrow;
                wscale = sc1;
            }
            float* orow = out + (size_t)token * HIDDEN;
            #pragma unroll
            for (int nt = 0; nt < 4; nt++) {
                int col = nb + wn * 32 + nt * 8 + 2 * lr;
                float2 bv = *(const float2*)&bias[col];
                float s0 = wscale * sigf(acc[mt][nt][2 * h]     + bv.x);
                float s1 = wscale * sigf(acc[mt][nt][2 * h + 1] + bv.y);
                red_add_v2(orow + col, s0, s1);
            }
        }
    }
}

// ---------------- K2: fused shared + expert GEMM (+ gate loss) ----------------
__global__ __launch_bounds__(256, 2)
void fused_gemm(const float* __restrict__ SBias, const float* __restrict__ p_ss,
                const float* __restrict__ EBias, const float* __restrict__ p_rs,
                float* __restrict__ out, int out_size)
{
    const int nb = blockIdx.y * TILE_N;
    const int mb = blockIdx.x * TILE_M;
    if (blockIdx.z == NEXP) {
        // gate loss (g_psum ready from mega_kernel)
        if (mb == 0 && nb == 0 && threadIdx.x == 0) {
            float acc = 0.f;
            #pragma unroll
            for (int e = 0; e < NEXP; e++) {
                float p = g_psum[e] * (1.f / (float)BTOK);
                float d = 0.125f - p;
                acc += d * d;
            }
            float loss = acc * (0.01f / 8.f);
            for (long long i = (long long)BTOK * HIDDEN; i < out_size; i++)
                out[i] = loss;
        }
        gemm_tile<false>(g_wb + (size_t)NEXP * HIDDEN * HIDDEN, SBias, p_ss[0],
                         out, mb, nb, BTOK, 0);
    } else {
        const int e = blockIdx.z;
        const int cnt = g_cnt[e];
        if (mb >= cnt) return;
        gemm_tile<true>(g_wb + (size_t)e * HIDDEN * HIDDEN,
                        EBias + (size_t)e * HIDDEN, p_rs[0], out, mb, nb, cnt, e);
    }
}

// ---------------- launcher ----------------
extern "C" void kernel_launch(void* const* d_in, const int* in_sizes, int n_in,
                              void* d_out, int out_size) {
    const float* x      = (const float*)d_in[0];
    const float* noise  = (const float*)d_in[1];
    const float* gw1    = (const float*)d_in[2];
    const float* gb1    = (const float*)d_in[3];
    const float* gw2    = (const float*)d_in[4];
    const float* gb2    = (const float*)d_in[5];
    const float* sw     = (const float*)d_in[6];
    const float* sb     = (const float*)d_in[7];
    const float* sscale = (const float*)d_in[8];
    const float* ew     = (const float*)d_in[9];
    const float* eb     = (const float*)d_in[10];
    const float* rscale = (const float*)d_in[11];
    float* out = (float*)d_out;

    static bool attr_done = false;
    if (!attr_done) {
        cudaFuncSetAttribute(fused_gemm, cudaFuncAttributeMaxDynamicSharedMemorySize, SMEM_TOTAL);
        attr_done = true;
    }

    init_kernel<<<1, 32>>>();
    mega_kernel<<<MEGA_BLOCKS, 256>>>(x, noise, gw1, gb1, gw2, gb2, ew, sw, rscale, out);
    fused_gemm<<<dim3(BTOK / TILE_M, HIDDEN / TILE_N, NEXP + 1), 256, SMEM_TOTAL>>>(
        sb, sscale, eb, rscale, out, out_size);
}